// round 14
// baseline (speedup 1.0000x reference)
#include <cuda_runtime.h>
#include <cuda_fp16.h>
#include <math.h>
#include <cstdint>

// Problem constants: B=4, S=2048, Hd=1024, H=8, dk=128, wA=67
#define NBH   32
#define SEQ   2048
#define DKD   128
#define WAW   67
#define OUT1_ELEMS (4*2048*536)

// ---------------- scratch: pre-split fp16 hi/lo (zero-init pads persist) ----
__device__ __align__(16) __half g_Qhi[NBH*SEQ*DKD];
__device__ __align__(16) __half g_Qlo[NBH*SEQ*DKD];
__device__ __align__(16) __half g_Khi[NBH*SEQ*DKD];
__device__ __align__(16) __half g_Klo[NBH*SEQ*DKD];
// cD transposed per 128-key-tile: (bh, kt128, w[72], key[128]); w=67..71 zero
__device__ __align__(16) __half g_cDhi[NBH*16*72*128];

__constant__ float c_lo[8] = { -0.010597401784997278f, 0.032883011666982945f,
                                0.030841381835986965f, -0.18703481171888114f,
                               -0.02798376941698385f,  0.6308807679295904f,
                                0.7148465705525415f,   0.23037781330885523f };
__constant__ float c_hi[8] = { -0.23037781330885523f,  0.7148465705525415f,
                               -0.6308807679295904f,  -0.02798376941698385f,
                                0.18703481171888114f,  0.030841381835986965f,
                               -0.032883011666982945f, -0.010597401784997278f };

__device__ __forceinline__ uint32_t f2tf32(float f) {
    uint32_t u;
    asm("cvt.rna.tf32.f32 %0, %1;" : "=r"(u) : "f"(f));
    return u;
}

// NOTE: NOT volatile — pure register ops; lets ptxas schedule/pipeline HMMA.
__device__ __forceinline__ void mma_tf32(float& d0, float& d1, float& d2, float& d3,
                                         uint32_t a0, uint32_t a1, uint32_t a2, uint32_t a3,
                                         uint32_t b0, uint32_t b1) {
    asm("mma.sync.aligned.m16n8k8.row.col.f32.tf32.tf32.f32 "
        "{%0,%1,%2,%3}, {%4,%5,%6,%7}, {%8,%9}, {%0,%1,%2,%3};"
        : "+f"(d0), "+f"(d1), "+f"(d2), "+f"(d3)
        : "r"(a0), "r"(a1), "r"(a2), "r"(a3), "r"(b0), "r"(b1));
}

__device__ __forceinline__ void mma_f16(float& d0, float& d1, float& d2, float& d3,
                                        uint32_t a0, uint32_t a1, uint32_t a2, uint32_t a3,
                                        uint32_t b0, uint32_t b1) {
    asm("mma.sync.aligned.m16n8k16.row.col.f32.f16.f16.f32 "
        "{%0,%1,%2,%3}, {%4,%5,%6,%7}, {%8,%9}, {%0,%1,%2,%3};"
        : "+f"(d0), "+f"(d1), "+f"(d2), "+f"(d3)
        : "r"(a0), "r"(a1), "r"(a2), "r"(a3), "r"(b0), "r"(b1));
}

__device__ __forceinline__ void ldsm_x4(uint32_t& r0, uint32_t& r1,
                                        uint32_t& r2, uint32_t& r3, uint32_t a) {
    asm volatile("ldmatrix.sync.aligned.m8n8.x4.shared.b16 {%0,%1,%2,%3}, [%4];"
                 : "=r"(r0), "=r"(r1), "=r"(r2), "=r"(r3) : "r"(a));
}
__device__ __forceinline__ void ldsm_x2(uint32_t& r0, uint32_t& r1, uint32_t a) {
    asm volatile("ldmatrix.sync.aligned.m8n8.x2.shared.b16 {%0,%1}, [%2];"
                 : "=r"(r0), "=r"(r1) : "r"(a));
}

__device__ __forceinline__ void split_h2(float x, float y, __half2& hi, __half2& lo) {
    hi = __float22half2_rn(make_float2(x, y));
    float2 b = __half22float2(hi);
    lo = __float22half2_rn(make_float2(x - b.x, y - b.y));
}

__device__ __forceinline__ void cp_async16(uint32_t saddr, const void* g) {
    asm volatile("cp.async.cg.shared.global [%0], [%1], 16;"
                 :: "r"(saddr), "l"(g) : "memory");
}
__device__ __forceinline__ void cp_commit() {
    asm volatile("cp.async.commit_group;" ::: "memory");
}
template<int N>
__device__ __forceinline__ void cp_wait() {
    asm volatile("cp.async.wait_group %0;" :: "n"(N) : "memory");
}

// ======================================================================
// Kernel 1: QKV projection (mma.sync tf32, now schedulable).
// ======================================================================
#define CHN 4608
#define QKV_SMEM (4*CHN*4)

__global__ __launch_bounds__(256, 2) void qkv_mma_kernel(
    const float* __restrict__ x, const float* __restrict__ Wq,
    const float* __restrict__ Wk, const float* __restrict__ Wv,
    float* __restrict__ out2)
{
    extern __shared__ float sm[];
    float* As = sm;
    float* Bs = sm + 2*CHN;

    const int tid  = threadIdx.x;
    const int lane = tid & 31;
    const int warp = tid >> 5;
    const int g    = lane >> 2;
    const int tig  = lane & 3;
    const int wm   = warp & 3;
    const int wn   = warp >> 2;

    const int which = blockIdx.z;
    const float* W = (which == 0) ? Wq : ((which == 1) ? Wk : Wv);
    const float scale = (which == 0) ? 0.08838834764831845f : 1.0f;

    const int m0   = blockIdx.y * 128;
    const int head = blockIdx.x;
    const float* xb = x + (size_t)m0 * 1024;
    const float* wb = W + (size_t)head * 128 * 1024;

    const int lr = tid >> 3;
    const int lc = (tid & 7) * 4;

    float c[2][8][4];
#pragma unroll
    for (int mt = 0; mt < 2; mt++)
#pragma unroll
        for (int nt = 0; nt < 8; nt++)
#pragma unroll
            for (int q = 0; q < 4; q++) c[mt][nt][q] = 0.0f;

    {
#pragma unroll
        for (int u = 0; u < 4; u++) {
            const int r = lr + 32*u;
            const float4 a4 = *(const float4*)(xb + (size_t)r*1024 + lc);
            const float4 b4 = *(const float4*)(wb + (size_t)r*1024 + lc);
            float* pa = As + r*36 + lc;
            float* pb = Bs + r*36 + lc;
            pa[0] = __uint_as_float(f2tf32(a4.x)); pa[1] = __uint_as_float(f2tf32(a4.y));
            pa[2] = __uint_as_float(f2tf32(a4.z)); pa[3] = __uint_as_float(f2tf32(a4.w));
            pb[0] = __uint_as_float(f2tf32(b4.x)); pb[1] = __uint_as_float(f2tf32(b4.y));
            pb[2] = __uint_as_float(f2tf32(b4.z)); pb[3] = __uint_as_float(f2tf32(b4.w));
        }
    }
    __syncthreads();

    for (int ch = 0; ch < 32; ch++) {
        const int cur = ch & 1;
        float4 pfa[4], pfb[4];
        if (ch < 31) {
            const int kb = (ch + 1) << 5;
#pragma unroll
            for (int u = 0; u < 4; u++) {
                const int r = lr + 32*u;
                pfa[u] = *(const float4*)(xb + (size_t)r*1024 + kb + lc);
                pfb[u] = *(const float4*)(wb + (size_t)r*1024 + kb + lc);
            }
        }

        const float* as = As + cur*CHN;
        const float* bs = Bs + cur*CHN;
#pragma unroll
        for (int ks = 0; ks < 4; ks++) {
            const int k0 = ks * 8;
            uint32_t a[2][4];
#pragma unroll
            for (int mt = 0; mt < 2; mt++) {
                const int rb = wm*32 + mt*16 + g;
                a[mt][0] = __float_as_uint(as[(rb    )*36 + k0 + tig]);
                a[mt][1] = __float_as_uint(as[(rb + 8)*36 + k0 + tig]);
                a[mt][2] = __float_as_uint(as[(rb    )*36 + k0 + tig + 4]);
                a[mt][3] = __float_as_uint(as[(rb + 8)*36 + k0 + tig + 4]);
            }
#pragma unroll
            for (int nt = 0; nt < 8; nt++) {
                const int nb = wn*64 + nt*8 + g;
                const uint32_t b0 = __float_as_uint(bs[nb*36 + k0 + tig]);
                const uint32_t b1 = __float_as_uint(bs[nb*36 + k0 + tig + 4]);
#pragma unroll
                for (int mt = 0; mt < 2; mt++)
                    mma_tf32(c[mt][nt][0], c[mt][nt][1], c[mt][nt][2], c[mt][nt][3],
                             a[mt][0], a[mt][1], a[mt][2], a[mt][3], b0, b1);
            }
        }

        if (ch < 31) {
            float* pa0 = As + (cur^1)*CHN;
            float* pb0 = Bs + (cur^1)*CHN;
#pragma unroll
            for (int u = 0; u < 4; u++) {
                const int r = lr + 32*u;
                float* pa = pa0 + r*36 + lc;
                float* pb = pb0 + r*36 + lc;
                pa[0] = __uint_as_float(f2tf32(pfa[u].x)); pa[1] = __uint_as_float(f2tf32(pfa[u].y));
                pa[2] = __uint_as_float(f2tf32(pfa[u].z)); pa[3] = __uint_as_float(f2tf32(pfa[u].w));
                pb[0] = __uint_as_float(f2tf32(pfb[u].x)); pb[1] = __uint_as_float(f2tf32(pfb[u].y));
                pb[2] = __uint_as_float(f2tf32(pfb[u].z)); pb[3] = __uint_as_float(f2tf32(pfb[u].w));
            }
        }
        __syncthreads();
    }

    if (which < 2) {
        __half2* Ohi = (which == 0) ? (__half2*)g_Qhi : (__half2*)g_Khi;
        __half2* Olo = (which == 0) ? (__half2*)g_Qlo : (__half2*)g_Klo;
#pragma unroll
        for (int mt = 0; mt < 2; mt++) {
            const int m  = m0 + wm*32 + mt*16 + g;
            const int b0_ = m >> 11, sq = m & 2047;
            const size_t row0 = ((size_t)(b0_*8 + head) * 2048 + sq) * 64;
            const size_t row1 = row0 + 8*64;
#pragma unroll
            for (int nt = 0; nt < 8; nt++) {
                const int d2 = wn*32 + nt*4 + tig;
                __half2 h, l;
                split_h2(c[mt][nt][0]*scale, c[mt][nt][1]*scale, h, l);
                Ohi[row0 + d2] = h;  Olo[row0 + d2] = l;
                split_h2(c[mt][nt][2]*scale, c[mt][nt][3]*scale, h, l);
                Ohi[row1 + d2] = h;  Olo[row1 + d2] = l;
            }
        }
    } else {
        float* Vt = sm;           // [128][132]
#pragma unroll
        for (int mt = 0; mt < 2; mt++) {
            const int r0 = wm*32 + mt*16 + g;
#pragma unroll
            for (int nt = 0; nt < 8; nt++) {
                const int d = wn*64 + nt*8 + 2*tig;
                *(float2*)(Vt + (r0    )*132 + d) = make_float2(c[mt][nt][0], c[mt][nt][1]);
                *(float2*)(Vt + (r0 + 8)*132 + d) = make_float2(c[mt][nt][2], c[mt][nt][3]);
            }
        }
        __syncthreads();
        const int r    = tid >> 1;
        const int half = tid & 1;
        const int m    = m0 + r;
        const int b0_  = m >> 11, sq = m & 2047;
        const int bh   = b0_*8 + head;
        const int kt_  = sq >> 7, key = sq & 127;
        const size_t rowbase = ((size_t)bh * 2048 + sq) * WAW;
        const size_t cdbase  = ((size_t)bh * 16 + kt_) * 72 * 128 + key;
        const float* v = Vt + r*132;
        for (int t = half; t < WAW; t += 2) {
            float a = 0.0f, d = 0.0f;
#pragma unroll
            for (int k = 0; k < 8; k++) {
                const int j = 2*t + k;
                const int src = (j < 6) ? (5 - j) : ((j < 134) ? (j - 6) : (261 - j));
                const float e = v[src];
                a = fmaf(e, c_lo[7 - k], a);
                d = fmaf(e, c_hi[7 - k], d);
            }
            out2[rowbase + t] = a;
            g_cDhi[cdbase + (size_t)t*128] = __float2half_rn(d);
        }
    }
}

// ======================================================================
// Kernel 2: flash attention, 64q x 64k, fp16 hi/lo (S), cD hi-only (PV).
// PV one tile behind fused with softmax; S-phase MMAs interleaved by
// hi/lo TERM across fragments -> dependency distance 4.
// ======================================================================
#define SH68 68
#define SH36 36
#define OQHI 0
#define OQLO 4352
#define OKHI 8704
#define OKLO 13056
#define OCD0 17408           // 72*36 = 2592 per buffer
#define OP0  22592           // 64*36 = 2304 per buffer
#define OCTRL 27200
#define FL_SMEM ((OCTRL + 448) * 4)   // 110,592 B
#define ROW68B (SH68*4)
#define ROW36B (SH36*4)
#define CDB (2592*4)
#define PBB (2304*4)

__global__ __launch_bounds__(256, 2) void flash_f16_kernel(float* __restrict__ out1)
{
    extern __shared__ __align__(16) uint32_t smw[];
    uint32_t* Qhi = smw + OQHI;
    uint32_t* Qlo = smw + OQLO;
    float* rmax = (float*)(smw + OCTRL);
    float* rsum = rmax + 128;
    float* m_s  = rsum + 128;
    float* l_s  = m_s + 64;
    float* al_s = l_s + 64;

    uint32_t sbase;
    asm("{ .reg .u64 t; cvta.to.shared.u64 t, %1; cvt.u32.u64 %0, t; }"
        : "=r"(sbase) : "l"(smw));
    const uint32_t khi_a = sbase + OKHI*4;
    const uint32_t klo_a = sbase + OKLO*4;
    const uint32_t cd_a  = sbase + OCD0*4;

    const int tid  = threadIdx.x;
    const int lane = tid & 31;
    const int warp = tid >> 5;
    const int g    = lane >> 2;
    const int tig  = lane & 3;
    const int wm   = warp & 3;
    const int wn   = warp >> 2;
    const int r4   = warp & 3;
    const int g2   = warp >> 2;

    const int bh = blockIdx.y;
    const int q0 = blockIdx.x * 64;
    const uint4* Qhig = (const uint4*)(g_Qhi + (size_t)bh * SEQ * DKD);
    const uint4* Qlog = (const uint4*)(g_Qlo + (size_t)bh * SEQ * DKD);
    const uint4* Khig = (const uint4*)(g_Khi + (size_t)bh * SEQ * DKD);
    const uint4* Klog = (const uint4*)(g_Klo + (size_t)bh * SEQ * DKD);

    const int cr  = tid >> 4;
    const int cc4 = tid & 15;

    const int rowf  = (lane & 7) + 8*((lane >> 3) & 1);
    const int colf4 = (lane >> 4) * 4;
    const int rowb  = (lane & 7) + 8*(lane >> 4);
    const int colb4 = ((lane >> 3) & 1) * 4;
    const uint32_t aq_hi = sbase + (OQHI + (wm*16 + rowf)*SH68 + colf4)*4;
    const uint32_t aq_lo = sbase + (OQLO + (wm*16 + rowf)*SH68 + colf4)*4;
    const uint32_t bk_hi = sbase + (OKHI + (wn*32 + rowb)*SH68 + colb4)*4;
    const uint32_t bk_lo = sbase + (OKLO + (wn*32 + rowb)*SH68 + colb4)*4;
    const uint32_t ap_b0 = sbase + (OP0 + (r4*16 + rowf)*SH36 + colf4)*4;
    const uint32_t cdh_b0 = sbase + (OCD0 + (g2*32 + rowb)*SH36 + colb4)*4;
    const uint32_t cdh8_0 = sbase + (OCD0 + (g2*32 + 32 + (lane & 7))*SH36 + colb4)*4;

    // ---- prefetch K(0) ----
#pragma unroll
    for (int u = 0; u < 4; u++) {
        const int r = cr + 16*u;
        cp_async16(khi_a + (r*SH68 + cc4*4)*4, Khig + (size_t)r*16 + cc4);
        cp_async16(klo_a + (r*SH68 + cc4*4)*4, Klog + (size_t)r*16 + cc4);
    }
    cp_commit();

    // ---- load Q ----
#pragma unroll
    for (int u = 0; u < 4; u++) {
        const int r = cr + 16*u;
        *(uint4*)&Qhi[r*SH68 + cc4*4] = Qhig[(size_t)(q0 + r)*16 + cc4];
        *(uint4*)&Qlo[r*SH68 + cc4*4] = Qlog[(size_t)(q0 + r)*16 + cc4];
    }
    if (tid < 64) { m_s[tid] = -1e30f; l_s[tid] = 0.0f; }

    float o[5][4];
#pragma unroll
    for (int f = 0; f < 5; f++)
#pragma unroll
        for (int q = 0; q < 4; q++) o[f][q] = 0.0f;

    for (int kt = 0; kt < 32; kt++) {
        cp_wait<0>();
        __syncthreads();
        // ---- cD(kt) prefetch (hi only) into buf[kt&1] ----
        {
            const uint4* ch = (const uint4*)(g_cDhi + ((size_t)bh*16 + (kt >> 1))*72*128);
            const int koff8 = (kt & 1) * 8;
            const uint32_t dst = cd_a + (kt & 1)*CDB;
#pragma unroll
            for (int u = 0; u < 3; u++) {
                const int i = tid + 256*u;
                if (i < 576) {
                    const int w = i >> 3, c = i & 7;
                    cp_async16(dst + (w*SH36 + c*4)*4, ch + (size_t)w*16 + koff8 + c);
                }
            }
            cp_commit();
        }

        // ---- S = Q K^T : LDSM + term-interleaved 3-MMA ----
        float s[4][4];
#pragma unroll
        for (int nt = 0; nt < 4; nt++)
#pragma unroll
            for (int q = 0; q < 4; q++) s[nt][q] = 0.0f;

#pragma unroll 2
        for (int ks = 0; ks < 8; ks++) {
            const uint32_t kb = ks * 32;
            uint32_t ah[4], al_[4];
            ldsm_x4(ah[0], ah[1], ah[2], ah[3], aq_hi + kb);
            ldsm_x4(al_[0], al_[1], al_[2], al_[3], aq_lo + kb);
            uint32_t bh_[2][4], bl_[2][4];
#pragma unroll
            for (int p = 0; p < 2; p++) {
                ldsm_x4(bh_[p][0], bh_[p][1], bh_[p][2], bh_[p][3], bk_hi + p*16*ROW68B + kb);
                ldsm_x4(bl_[p][0], bl_[p][1], bl_[p][2], bl_[p][3], bk_lo + p*16*ROW68B + kb);
            }
            // term hh: 4 independent accumulators
#pragma unroll
            for (int p = 0; p < 2; p++) {
                mma_f16(s[2*p][0], s[2*p][1], s[2*p][2], s[2*p][3],
                        ah[0], ah[1], ah[2], ah[3], bh_[p][0], bh_[p][1]);
                mma_f16(s[2*p+1][0], s[2*p+1][1], s[2*p+1][2], s[2*p+1][3],
                        ah[0], ah[1], ah[2], ah[3], bh_[p][2], bh_[p][3]);
            }
            // term hl
#pragma unroll
            for (int p = 0; p < 2; p++) {
                mma_f16(s[2*p][0], s[2*p][1], s[2*p][2], s[2*p][3],
                        ah[0], ah[1], ah[2], ah[3], bl_[p][0], bl_[p][1]);
                mma_f16(s[2*p+1][0], s[2*p+1][1], s[2*p+1][2], s[2*p+1][3],
                        ah[0], ah[1], ah[2], ah[3], bl_[p][2], bl_[p][3]);
            }
            // term lh
#pragma unroll
            for (int p = 0; p < 2; p++) {
                mma_f16(s[2*p][0], s[2*p][1], s[2*p][2], s[2*p][3],
                        al_[0], al_[1], al_[2], al_[3], bh_[p][0], bh_[p][1]);
                mma_f16(s[2*p+1][0], s[2*p+1][1], s[2*p+1][2], s[2*p+1][3],
                        al_[0], al_[1], al_[2], al_[3], bh_[p][2], bh_[p][3]);
            }
        }

        // ---- row max ----
        float mx[2];
#pragma unroll
        for (int hf = 0; hf < 2; hf++) {
            float m = -1e30f;
#pragma unroll
            for (int nt = 0; nt < 4; nt++)
                m = fmaxf(m, fmaxf(s[nt][2*hf], s[nt][2*hf+1]));
            m = fmaxf(m, __shfl_xor_sync(0xffffffffu, m, 1));
            m = fmaxf(m, __shfl_xor_sync(0xffffffffu, m, 2));
            mx[hf] = m;
        }
        if (tig == 0) {
#pragma unroll
            for (int hf = 0; hf < 2; hf++)
                rmax[(wm*16 + g + 8*hf)*2 + wn] = mx[hf];
        }
        __syncthreads();

        // ---- prefetch K(kt+1) ----
        if (kt < 31) {
            const int n1 = (kt + 1) * 64;
#pragma unroll
            for (int u = 0; u < 4; u++) {
                const int r = cr + 16*u;
                cp_async16(khi_a + (r*SH68 + cc4*4)*4, Khig + (size_t)(n1 + r)*16 + cc4);
                cp_async16(klo_a + (r*SH68 + cc4*4)*4, Klog + (size_t)(n1 + r)*16 + cc4);
            }
            cp_commit();
        }

        // ======= BARRIER-FREE REGION: PV(kt-1) HMMA ∥ softmax(kt) =======
        float mnew[2], alv[2], ssum[2];
#pragma unroll
        for (int hf = 0; hf < 2; hf++) {
            const int row = wm*16 + g + 8*hf;
            const float tm = fmaxf(rmax[row*2], rmax[row*2+1]);
            const float mo = m_s[row];
            const float mn = fmaxf(mo, tm);
            mnew[hf] = mn;
            alv[hf]  = __expf(mo - mn);
            ssum[hf] = 0.0f;
        }

        if (kt > 0) {
            const int rb = r4*16 + g;
            const float a0 = al_s[rb], a1 = al_s[rb + 8];
#pragma unroll
            for (int f = 0; f < 5; f++) {
                o[f][0] *= a0; o[f][1] *= a0;
                o[f][2] *= a1; o[f][3] *= a1;
            }
            const uint32_t pbuf = ap_b0  + ((kt-1) & 1)*PBB;
            const uint32_t cbuf = cdh_b0 + ((kt-1) & 1)*CDB;
            const uint32_t cbuf8 = cdh8_0 + ((kt-1) & 1)*CDB;
#pragma unroll
            for (int ks = 0; ks < 4; ks++) {
                const uint32_t kb = ks * 32;
                uint32_t ph[4];
                ldsm_x4(ph[0], ph[1], ph[2], ph[3], pbuf + kb);
#pragma unroll
                for (int p = 0; p < 2; p++) {
                    uint32_t c0A, c1A, c0B, c1B;
                    ldsm_x4(c0A, c1A, c0B, c1B, cbuf + p*16*ROW36B + kb);
                    const int f0 = 2*p, f1 = 2*p + 1;
                    mma_f16(o[f0][0], o[f0][1], o[f0][2], o[f0][3],
                            ph[0], ph[1], ph[2], ph[3], c0A, c1A);
                    mma_f16(o[f1][0], o[f1][1], o[f1][2], o[f1][3],
                            ph[0], ph[1], ph[2], ph[3], c0B, c1B);
                }
                {
                    uint32_t c80, c81;
                    ldsm_x2(c80, c81, cbuf8 + kb);
                    mma_f16(o[4][0], o[4][1], o[4][2], o[4][3],
                            ph[0], ph[1], ph[2], ph[3], c80, c81);
                }
            }
        }

        {   // softmax(kt)
            uint32_t* Pw = smw + OP0 + (kt & 1)*2304;
            const int r0 = wm*16 + g;
#pragma unroll
            for (int nt = 0; nt < 4; nt++) {
                const int cb = 16*wn + 4*nt + tig;
                float p0 = __expf(s[nt][0] - mnew[0]);
                float p1 = __expf(s[nt][1] - mnew[0]);
                float p2 = __expf(s[nt][2] - mnew[1]);
                float p3 = __expf(s[nt][3] - mnew[1]);
                ssum[0] += p0 + p1;
                ssum[1] += p2 + p3;
                __half2 h;
                h = __float22half2_rn(make_float2(p0, p1));
                Pw[(r0    )*SH36 + cb] = *(uint32_t*)&h;
                h = __float22half2_rn(make_float2(p2, p3));
                Pw[(r0 + 8)*SH36 + cb] = *(uint32_t*)&h;
            }
        }
#pragma unroll
        for (int hf = 0; hf < 2; hf++) {
            float sv = ssum[hf];
            sv += __shfl_xor_sync(0xffffffffu, sv, 1);
            sv += __shfl_xor_sync(0xffffffffu, sv, 2);
            if (tig == 0) rsum[(wm*16 + g + 8*hf)*2 + wn] = sv;
        }
        __syncthreads();
        // ======= end region =======

        if (wn == 0 && tig == 0) {
#pragma unroll
            for (int hf = 0; hf < 2; hf++) {
                const int row = wm*16 + g + 8*hf;
                const float ts = rsum[row*2] + rsum[row*2+1];
                l_s[row]  = l_s[row]*alv[hf] + ts;
                m_s[row]  = mnew[hf];
                al_s[row] = alv[hf];
            }
        }
        if (kt < 31) cp_wait<1>(); else cp_wait<0>();
        __syncthreads();
    }

    // ---- epilogue PV(31) ----
    {
        const int rb = r4*16 + g;
        const float a0 = al_s[rb], a1 = al_s[rb + 8];
#pragma unroll
        for (int f = 0; f < 5; f++) {
            o[f][0] *= a0; o[f][1] *= a0;
            o[f][2] *= a1; o[f][3] *= a1;
        }
        const uint32_t pbuf = ap_b0  + (31 & 1)*PBB;
        const uint32_t cbuf = cdh_b0 + (31 & 1)*CDB;
        const uint32_t cbuf8 = cdh8_0 + (31 & 1)*CDB;
#pragma unroll
        for (int ks = 0; ks < 4; ks++) {
            const uint32_t kb = ks * 32;
            uint32_t ph[4];
            ldsm_x4(ph[0], ph[1], ph[2], ph[3], pbuf + kb);
#pragma unroll
            for (int p = 0; p < 2; p++) {
                uint32_t c0A, c1A, c0B, c1B;
                ldsm_x4(c0A, c1A, c0B, c1B, cbuf + p*16*ROW36B + kb);
                const int f0 = 2*p, f1 = 2*p + 1;
                mma_f16(o[f0][0], o[f0][1], o[f0][2], o[f0][3],
                        ph[0], ph[1], ph[2], ph[3], c0A, c1A);
                mma_f16(o[f1][0], o[f1][1], o[f1][2], o[f1][3],
                        ph[0], ph[1], ph[2], ph[3], c0B, c1B);
            }
            {
                uint32_t c80, c81;
                ldsm_x2(c80, c81, cbuf8 + kb);
                mma_f16(o[4][0], o[4][1], o[4][2], o[4][3],
                        ph[0], ph[1], ph[2], ph[3], c80, c81);
            }
        }
    }

    // ---- store out1 ----
    const int rb = r4*16 + g;
    const float inv0 = 1.0f / l_s[rb];
    const float inv1 = 1.0f / l_s[rb + 8];
    const int b = bh >> 3, h = bh & 7;
    const size_t base0 = (size_t)(b*2048 + q0 + rb) * 536 + h*67;
    const size_t base1 = base0 + (size_t)8 * 536;
#pragma unroll
    for (int f = 0; f < 5; f++) {
        if (g2 == 1 && f == 0) continue;
        const int nt = g2*4 + f;
        const int col = nt*8 + 2*tig;
        if (col < WAW) {
            out1[base0 + col] = o[f][0] * inv0;
            out1[base1 + col] = o[f][2] * inv1;
        }
        if (col + 1 < WAW) {
            out1[base0 + col + 1] = o[f][1] * inv0;
            out1[base1 + col + 1] = o[f][3] * inv1;
        }
    }
}

// ======================================================================
extern "C" void kernel_launch(void* const* d_in, const int* in_sizes, int n_in,
                              void* d_out, int out_size)
{
    (void)in_sizes; (void)n_in; (void)out_size;
    const float* x  = (const float*)d_in[0];
    const float* Wq = (const float*)d_in[1];
    const float* Wk = (const float*)d_in[2];
    const float* Wv = (const float*)d_in[3];
    float* out = (float*)d_out;

    cudaFuncSetAttribute(qkv_mma_kernel, cudaFuncAttributeMaxDynamicSharedMemorySize,
                         QKV_SMEM);
    qkv_mma_kernel<<<dim3(8, 64, 3), 256, QKV_SMEM>>>(x, Wq, Wk, Wv,
                                                      out + OUT1_ELEMS);

    cudaFuncSetAttribute(flash_f16_kernel, cudaFuncAttributeMaxDynamicSharedMemorySize,
                         FL_SMEM);
    flash_f16_kernel<<<dim3(32, 32), 256, FL_SMEM>>>(out);
}

// round 15
// speedup vs baseline: 1.1655x; 1.1655x over previous
#include <cuda_runtime.h>
#include <cuda_fp16.h>
#include <math.h>
#include <cstdint>

// Problem constants: B=4, S=2048, Hd=1024, H=8, dk=128, wA=67
#define NBH   32
#define SEQ   2048
#define DKD   128
#define WAW   67
#define OUT1_ELEMS (4*2048*536)

// ---------------- scratch: pre-split fp16 (zero-init pads persist) ----
__device__ __align__(16) __half g_Qhi[NBH*SEQ*DKD];
__device__ __align__(16) __half g_Qlo[NBH*SEQ*DKD];
__device__ __align__(16) __half g_Khi[NBH*SEQ*DKD];     // K: hi only
// cD transposed per 128-key-tile: (bh, kt128, w[72], key[128]); w=67..71 zero
__device__ __align__(16) __half g_cDhi[NBH*16*72*128];

__constant__ float c_lo[8] = { -0.010597401784997278f, 0.032883011666982945f,
                                0.030841381835986965f, -0.18703481171888114f,
                               -0.02798376941698385f,  0.6308807679295904f,
                                0.7148465705525415f,   0.23037781330885523f };
__constant__ float c_hi[8] = { -0.23037781330885523f,  0.7148465705525415f,
                               -0.6308807679295904f,  -0.02798376941698385f,
                                0.18703481171888114f,  0.030841381835986965f,
                               -0.032883011666982945f, -0.010597401784997278f };

__device__ __forceinline__ uint32_t f2tf32(float f) {
    uint32_t u;
    asm("cvt.rna.tf32.f32 %0, %1;" : "=r"(u) : "f"(f));
    return u;
}

__device__ __forceinline__ void mma_tf32(float& d0, float& d1, float& d2, float& d3,
                                         uint32_t a0, uint32_t a1, uint32_t a2, uint32_t a3,
                                         uint32_t b0, uint32_t b1) {
    asm("mma.sync.aligned.m16n8k8.row.col.f32.tf32.tf32.f32 "
        "{%0,%1,%2,%3}, {%4,%5,%6,%7}, {%8,%9}, {%0,%1,%2,%3};"
        : "+f"(d0), "+f"(d1), "+f"(d2), "+f"(d3)
        : "r"(a0), "r"(a1), "r"(a2), "r"(a3), "r"(b0), "r"(b1));
}

__device__ __forceinline__ void mma_f16(float& d0, float& d1, float& d2, float& d3,
                                        uint32_t a0, uint32_t a1, uint32_t a2, uint32_t a3,
                                        uint32_t b0, uint32_t b1) {
    asm("mma.sync.aligned.m16n8k16.row.col.f32.f16.f16.f32 "
        "{%0,%1,%2,%3}, {%4,%5,%6,%7}, {%8,%9}, {%0,%1,%2,%3};"
        : "+f"(d0), "+f"(d1), "+f"(d2), "+f"(d3)
        : "r"(a0), "r"(a1), "r"(a2), "r"(a3), "r"(b0), "r"(b1));
}

__device__ __forceinline__ void ldsm_x4(uint32_t& r0, uint32_t& r1,
                                        uint32_t& r2, uint32_t& r3, uint32_t a) {
    asm volatile("ldmatrix.sync.aligned.m8n8.x4.shared.b16 {%0,%1,%2,%3}, [%4];"
                 : "=r"(r0), "=r"(r1), "=r"(r2), "=r"(r3) : "r"(a));
}
__device__ __forceinline__ void ldsm_x2(uint32_t& r0, uint32_t& r1, uint32_t a) {
    asm volatile("ldmatrix.sync.aligned.m8n8.x2.shared.b16 {%0,%1}, [%2];"
                 : "=r"(r0), "=r"(r1) : "r"(a));
}

__device__ __forceinline__ void split_h2(float x, float y, __half2& hi, __half2& lo) {
    hi = __float22half2_rn(make_float2(x, y));
    float2 b = __half22float2(hi);
    lo = __float22half2_rn(make_float2(x - b.x, y - b.y));
}

__device__ __forceinline__ void cp_async16(uint32_t saddr, const void* g) {
    asm volatile("cp.async.cg.shared.global [%0], [%1], 16;"
                 :: "r"(saddr), "l"(g) : "memory");
}
__device__ __forceinline__ void cp_commit() {
    asm volatile("cp.async.commit_group;" ::: "memory");
}
template<int N>
__device__ __forceinline__ void cp_wait() {
    asm volatile("cp.async.wait_group %0;" :: "n"(N) : "memory");
}

// ======================================================================
// Kernel 1: QKV projection (mma.sync tf32).  Q -> hi/lo split; K -> hi
// only; V-epilogue fuses db4 DWT, writes cD (hi only) transposed.
// ======================================================================
#define CHN 4608
#define QKV_SMEM (4*CHN*4)

__global__ __launch_bounds__(256, 2) void qkv_mma_kernel(
    const float* __restrict__ x, const float* __restrict__ Wq,
    const float* __restrict__ Wk, const float* __restrict__ Wv,
    float* __restrict__ out2)
{
    extern __shared__ float sm[];
    float* As = sm;
    float* Bs = sm + 2*CHN;

    const int tid  = threadIdx.x;
    const int lane = tid & 31;
    const int warp = tid >> 5;
    const int g    = lane >> 2;
    const int tig  = lane & 3;
    const int wm   = warp & 3;
    const int wn   = warp >> 2;

    const int which = blockIdx.z;
    const float* W = (which == 0) ? Wq : ((which == 1) ? Wk : Wv);
    const float scale = (which == 0) ? 0.08838834764831845f : 1.0f;

    const int m0   = blockIdx.y * 128;
    const int head = blockIdx.x;
    const float* xb = x + (size_t)m0 * 1024;
    const float* wb = W + (size_t)head * 128 * 1024;

    const int lr = tid >> 3;
    const int lc = (tid & 7) * 4;

    float c[2][8][4];
#pragma unroll
    for (int mt = 0; mt < 2; mt++)
#pragma unroll
        for (int nt = 0; nt < 8; nt++)
#pragma unroll
            for (int q = 0; q < 4; q++) c[mt][nt][q] = 0.0f;

    {
#pragma unroll
        for (int u = 0; u < 4; u++) {
            const int r = lr + 32*u;
            const float4 a4 = *(const float4*)(xb + (size_t)r*1024 + lc);
            const float4 b4 = *(const float4*)(wb + (size_t)r*1024 + lc);
            float* pa = As + r*36 + lc;
            float* pb = Bs + r*36 + lc;
            pa[0] = __uint_as_float(f2tf32(a4.x)); pa[1] = __uint_as_float(f2tf32(a4.y));
            pa[2] = __uint_as_float(f2tf32(a4.z)); pa[3] = __uint_as_float(f2tf32(a4.w));
            pb[0] = __uint_as_float(f2tf32(b4.x)); pb[1] = __uint_as_float(f2tf32(b4.y));
            pb[2] = __uint_as_float(f2tf32(b4.z)); pb[3] = __uint_as_float(f2tf32(b4.w));
        }
    }
    __syncthreads();

    for (int ch = 0; ch < 32; ch++) {
        const int cur = ch & 1;
        float4 pfa[4], pfb[4];
        if (ch < 31) {
            const int kb = (ch + 1) << 5;
#pragma unroll
            for (int u = 0; u < 4; u++) {
                const int r = lr + 32*u;
                pfa[u] = *(const float4*)(xb + (size_t)r*1024 + kb + lc);
                pfb[u] = *(const float4*)(wb + (size_t)r*1024 + kb + lc);
            }
        }

        const float* as = As + cur*CHN;
        const float* bs = Bs + cur*CHN;
#pragma unroll
        for (int ks = 0; ks < 4; ks++) {
            const int k0 = ks * 8;
            uint32_t a[2][4];
#pragma unroll
            for (int mt = 0; mt < 2; mt++) {
                const int rb = wm*32 + mt*16 + g;
                a[mt][0] = __float_as_uint(as[(rb    )*36 + k0 + tig]);
                a[mt][1] = __float_as_uint(as[(rb + 8)*36 + k0 + tig]);
                a[mt][2] = __float_as_uint(as[(rb    )*36 + k0 + tig + 4]);
                a[mt][3] = __float_as_uint(as[(rb + 8)*36 + k0 + tig + 4]);
            }
#pragma unroll
            for (int nt = 0; nt < 8; nt++) {
                const int nb = wn*64 + nt*8 + g;
                const uint32_t b0 = __float_as_uint(bs[nb*36 + k0 + tig]);
                const uint32_t b1 = __float_as_uint(bs[nb*36 + k0 + tig + 4]);
#pragma unroll
                for (int mt = 0; mt < 2; mt++)
                    mma_tf32(c[mt][nt][0], c[mt][nt][1], c[mt][nt][2], c[mt][nt][3],
                             a[mt][0], a[mt][1], a[mt][2], a[mt][3], b0, b1);
            }
        }

        if (ch < 31) {
            float* pa0 = As + (cur^1)*CHN;
            float* pb0 = Bs + (cur^1)*CHN;
#pragma unroll
            for (int u = 0; u < 4; u++) {
                const int r = lr + 32*u;
                float* pa = pa0 + r*36 + lc;
                float* pb = pb0 + r*36 + lc;
                pa[0] = __uint_as_float(f2tf32(pfa[u].x)); pa[1] = __uint_as_float(f2tf32(pfa[u].y));
                pa[2] = __uint_as_float(f2tf32(pfa[u].z)); pa[3] = __uint_as_float(f2tf32(pfa[u].w));
                pb[0] = __uint_as_float(f2tf32(pfb[u].x)); pb[1] = __uint_as_float(f2tf32(pfb[u].y));
                pb[2] = __uint_as_float(f2tf32(pfb[u].z)); pb[3] = __uint_as_float(f2tf32(pfb[u].w));
            }
        }
        __syncthreads();
    }

    if (which == 0) {
        // Q: hi/lo split, pre-scaled
        __half2* Ohi = (__half2*)g_Qhi;
        __half2* Olo = (__half2*)g_Qlo;
#pragma unroll
        for (int mt = 0; mt < 2; mt++) {
            const int m  = m0 + wm*32 + mt*16 + g;
            const int b0_ = m >> 11, sq = m & 2047;
            const size_t row0 = ((size_t)(b0_*8 + head) * 2048 + sq) * 64;
            const size_t row1 = row0 + 8*64;
#pragma unroll
            for (int nt = 0; nt < 8; nt++) {
                const int d2 = wn*32 + nt*4 + tig;
                __half2 h, l;
                split_h2(c[mt][nt][0]*scale, c[mt][nt][1]*scale, h, l);
                Ohi[row0 + d2] = h;  Olo[row0 + d2] = l;
                split_h2(c[mt][nt][2]*scale, c[mt][nt][3]*scale, h, l);
                Ohi[row1 + d2] = h;  Olo[row1 + d2] = l;
            }
        }
    } else if (which == 1) {
        // K: hi only
        __half2* Ohi = (__half2*)g_Khi;
#pragma unroll
        for (int mt = 0; mt < 2; mt++) {
            const int m  = m0 + wm*32 + mt*16 + g;
            const int b0_ = m >> 11, sq = m & 2047;
            const size_t row0 = ((size_t)(b0_*8 + head) * 2048 + sq) * 64;
            const size_t row1 = row0 + 8*64;
#pragma unroll
            for (int nt = 0; nt < 8; nt++) {
                const int d2 = wn*32 + nt*4 + tig;
                Ohi[row0 + d2] = __float22half2_rn(make_float2(c[mt][nt][0], c[mt][nt][1]));
                Ohi[row1 + d2] = __float22half2_rn(make_float2(c[mt][nt][2], c[mt][nt][3]));
            }
        }
    } else {
        float* Vt = sm;           // [128][132]
#pragma unroll
        for (int mt = 0; mt < 2; mt++) {
            const int r0 = wm*32 + mt*16 + g;
#pragma unroll
            for (int nt = 0; nt < 8; nt++) {
                const int d = wn*64 + nt*8 + 2*tig;
                *(float2*)(Vt + (r0    )*132 + d) = make_float2(c[mt][nt][0], c[mt][nt][1]);
                *(float2*)(Vt + (r0 + 8)*132 + d) = make_float2(c[mt][nt][2], c[mt][nt][3]);
            }
        }
        __syncthreads();
        const int r    = tid >> 1;
        const int half = tid & 1;
        const int m    = m0 + r;
        const int b0_  = m >> 11, sq = m & 2047;
        const int bh   = b0_*8 + head;
        const int kt_  = sq >> 7, key = sq & 127;
        const size_t rowbase = ((size_t)bh * 2048 + sq) * WAW;
        const size_t cdbase  = ((size_t)bh * 16 + kt_) * 72 * 128 + key;
        const float* v = Vt + r*132;
        for (int t = half; t < WAW; t += 2) {
            float a = 0.0f, d = 0.0f;
#pragma unroll
            for (int k = 0; k < 8; k++) {
                const int j = 2*t + k;
                const int src = (j < 6) ? (5 - j) : ((j < 134) ? (j - 6) : (261 - j));
                const float e = v[src];
                a = fmaf(e, c_lo[7 - k], a);
                d = fmaf(e, c_hi[7 - k], d);
            }
            out2[rowbase + t] = a;
            g_cDhi[cdbase + (size_t)t*128] = __float2half_rn(d);
        }
    }
}

// ======================================================================
// Kernel 2: flash attention, 64q x 64k.  S = (Qhi+Qlo) x Khi (2 MMAs);
// PV = Phi x cDhi (1 MMA), one tile behind, fused with softmax.
// K hi-only -> SMEM 93 KB, 2 CTAs/SM.
// ======================================================================
#define SH68 68
#define SH36 36
#define OQHI 0
#define OQLO 4352
#define OKHI 8704
#define OCD0 13056           // 72*36 = 2592 per buffer (x2)
#define OP0  18240           // 64*36 = 2304 per buffer (x2)
#define OCTRL 22848
#define FL_SMEM ((OCTRL + 448) * 4)   // 93,184 B
#define ROW68B (SH68*4)
#define ROW36B (SH36*4)
#define CDB (2592*4)
#define PBB (2304*4)

__global__ __launch_bounds__(256, 2) void flash_f16_kernel(float* __restrict__ out1)
{
    extern __shared__ __align__(16) uint32_t smw[];
    uint32_t* Qhi = smw + OQHI;
    uint32_t* Qlo = smw + OQLO;
    float* rmax = (float*)(smw + OCTRL);
    float* rsum = rmax + 128;
    float* m_s  = rsum + 128;
    float* l_s  = m_s + 64;
    float* al_s = l_s + 64;

    uint32_t sbase;
    asm("{ .reg .u64 t; cvta.to.shared.u64 t, %1; cvt.u32.u64 %0, t; }"
        : "=r"(sbase) : "l"(smw));
    const uint32_t khi_a = sbase + OKHI*4;
    const uint32_t cd_a  = sbase + OCD0*4;

    const int tid  = threadIdx.x;
    const int lane = tid & 31;
    const int warp = tid >> 5;
    const int g    = lane >> 2;
    const int tig  = lane & 3;
    const int wm   = warp & 3;
    const int wn   = warp >> 2;
    const int r4   = warp & 3;
    const int g2   = warp >> 2;

    const int bh = blockIdx.y;
    const int q0 = blockIdx.x * 64;
    const uint4* Qhig = (const uint4*)(g_Qhi + (size_t)bh * SEQ * DKD);
    const uint4* Qlog = (const uint4*)(g_Qlo + (size_t)bh * SEQ * DKD);
    const uint4* Khig = (const uint4*)(g_Khi + (size_t)bh * SEQ * DKD);

    const int cr  = tid >> 4;
    const int cc4 = tid & 15;

    const int rowf  = (lane & 7) + 8*((lane >> 3) & 1);
    const int colf4 = (lane >> 4) * 4;
    const int rowb  = (lane & 7) + 8*(lane >> 4);
    const int colb4 = ((lane >> 3) & 1) * 4;
    const uint32_t aq_hi = sbase + (OQHI + (wm*16 + rowf)*SH68 + colf4)*4;
    const uint32_t aq_lo = sbase + (OQLO + (wm*16 + rowf)*SH68 + colf4)*4;
    const uint32_t bk_hi = sbase + (OKHI + (wn*32 + rowb)*SH68 + colb4)*4;
    const uint32_t ap_b0 = sbase + (OP0 + (r4*16 + rowf)*SH36 + colf4)*4;
    const uint32_t cdh_b0 = sbase + (OCD0 + (g2*32 + rowb)*SH36 + colb4)*4;
    const uint32_t cdh8_0 = sbase + (OCD0 + (g2*32 + 32 + (lane & 7))*SH36 + colb4)*4;

    // ---- prefetch K(0): hi only, 1024 uint4 ----
#pragma unroll
    for (int u = 0; u < 4; u++) {
        const int r = cr + 16*u;
        cp_async16(khi_a + (r*SH68 + cc4*4)*4, Khig + (size_t)r*16 + cc4);
    }
    cp_commit();

    // ---- load Q ----
#pragma unroll
    for (int u = 0; u < 4; u++) {
        const int r = cr + 16*u;
        *(uint4*)&Qhi[r*SH68 + cc4*4] = Qhig[(size_t)(q0 + r)*16 + cc4];
        *(uint4*)&Qlo[r*SH68 + cc4*4] = Qlog[(size_t)(q0 + r)*16 + cc4];
    }
    if (tid < 64) { m_s[tid] = -1e30f; l_s[tid] = 0.0f; }

    float o[5][4];
#pragma unroll
    for (int f = 0; f < 5; f++)
#pragma unroll
        for (int q = 0; q < 4; q++) o[f][q] = 0.0f;

    for (int kt = 0; kt < 32; kt++) {
        cp_wait<0>();
        __syncthreads();
        // ---- cD(kt) prefetch (hi only) into buf[kt&1] ----
        {
            const uint4* ch = (const uint4*)(g_cDhi + ((size_t)bh*16 + (kt >> 1))*72*128);
            const int koff8 = (kt & 1) * 8;
            const uint32_t dst = cd_a + (kt & 1)*CDB;
#pragma unroll
            for (int u = 0; u < 3; u++) {
                const int i = tid + 256*u;
                if (i < 576) {
                    const int w = i >> 3, c = i & 7;
                    cp_async16(dst + (w*SH36 + c*4)*4, ch + (size_t)w*16 + koff8 + c);
                }
            }
            cp_commit();
        }

        // ---- S = (Qhi + Qlo) x Khi : LDSM + 2 MMAs per fragment ----
        float s[4][4];
#pragma unroll
        for (int nt = 0; nt < 4; nt++)
#pragma unroll
            for (int q = 0; q < 4; q++) s[nt][q] = 0.0f;

#pragma unroll 2
        for (int ks = 0; ks < 8; ks++) {
            const uint32_t kb = ks * 32;
            uint32_t ah[4], al_[4];
            ldsm_x4(ah[0], ah[1], ah[2], ah[3], aq_hi + kb);
            ldsm_x4(al_[0], al_[1], al_[2], al_[3], aq_lo + kb);
            uint32_t bh_[2][4];
#pragma unroll
            for (int p = 0; p < 2; p++)
                ldsm_x4(bh_[p][0], bh_[p][1], bh_[p][2], bh_[p][3], bk_hi + p*16*ROW68B + kb);
            // term hh: 4 independent accumulators
#pragma unroll
            for (int p = 0; p < 2; p++) {
                mma_f16(s[2*p][0], s[2*p][1], s[2*p][2], s[2*p][3],
                        ah[0], ah[1], ah[2], ah[3], bh_[p][0], bh_[p][1]);
                mma_f16(s[2*p+1][0], s[2*p+1][1], s[2*p+1][2], s[2*p+1][3],
                        ah[0], ah[1], ah[2], ah[3], bh_[p][2], bh_[p][3]);
            }
            // term lh
#pragma unroll
            for (int p = 0; p < 2; p++) {
                mma_f16(s[2*p][0], s[2*p][1], s[2*p][2], s[2*p][3],
                        al_[0], al_[1], al_[2], al_[3], bh_[p][0], bh_[p][1]);
                mma_f16(s[2*p+1][0], s[2*p+1][1], s[2*p+1][2], s[2*p+1][3],
                        al_[0], al_[1], al_[2], al_[3], bh_[p][2], bh_[p][3]);
            }
        }

        // ---- row max ----
        float mx[2];
#pragma unroll
        for (int hf = 0; hf < 2; hf++) {
            float m = -1e30f;
#pragma unroll
            for (int nt = 0; nt < 4; nt++)
                m = fmaxf(m, fmaxf(s[nt][2*hf], s[nt][2*hf+1]));
            m = fmaxf(m, __shfl_xor_sync(0xffffffffu, m, 1));
            m = fmaxf(m, __shfl_xor_sync(0xffffffffu, m, 2));
            mx[hf] = m;
        }
        if (tig == 0) {
#pragma unroll
            for (int hf = 0; hf < 2; hf++)
                rmax[(wm*16 + g + 8*hf)*2 + wn] = mx[hf];
        }
        __syncthreads();

        // ---- prefetch K(kt+1) ----
        if (kt < 31) {
            const int n1 = (kt + 1) * 64;
#pragma unroll
            for (int u = 0; u < 4; u++) {
                const int r = cr + 16*u;
                cp_async16(khi_a + (r*SH68 + cc4*4)*4, Khig + (size_t)(n1 + r)*16 + cc4);
            }
            cp_commit();
        }

        // ======= BARRIER-FREE REGION: PV(kt-1) HMMA ∥ softmax(kt) =======
        float mnew[2], alv[2], ssum[2];
#pragma unroll
        for (int hf = 0; hf < 2; hf++) {
            const int row = wm*16 + g + 8*hf;
            const float tm = fmaxf(rmax[row*2], rmax[row*2+1]);
            const float mo = m_s[row];
            const float mn = fmaxf(mo, tm);
            mnew[hf] = mn;
            alv[hf]  = __expf(mo - mn);
            ssum[hf] = 0.0f;
        }

        if (kt > 0) {
            const int rb = r4*16 + g;
            const float a0 = al_s[rb], a1 = al_s[rb + 8];
#pragma unroll
            for (int f = 0; f < 5; f++) {
                o[f][0] *= a0; o[f][1] *= a0;
                o[f][2] *= a1; o[f][3] *= a1;
            }
            const uint32_t pbuf = ap_b0  + ((kt-1) & 1)*PBB;
            const uint32_t cbuf = cdh_b0 + ((kt-1) & 1)*CDB;
            const uint32_t cbuf8 = cdh8_0 + ((kt-1) & 1)*CDB;
#pragma unroll
            for (int ks = 0; ks < 4; ks++) {
                const uint32_t kb = ks * 32;
                uint32_t ph[4];
                ldsm_x4(ph[0], ph[1], ph[2], ph[3], pbuf + kb);
#pragma unroll
                for (int p = 0; p < 2; p++) {
                    uint32_t c0A, c1A, c0B, c1B;
                    ldsm_x4(c0A, c1A, c0B, c1B, cbuf + p*16*ROW36B + kb);
                    const int f0 = 2*p, f1 = 2*p + 1;
                    mma_f16(o[f0][0], o[f0][1], o[f0][2], o[f0][3],
                            ph[0], ph[1], ph[2], ph[3], c0A, c1A);
                    mma_f16(o[f1][0], o[f1][1], o[f1][2], o[f1][3],
                            ph[0], ph[1], ph[2], ph[3], c0B, c1B);
                }
                {
                    uint32_t c80, c81;
                    ldsm_x2(c80, c81, cbuf8 + kb);
                    mma_f16(o[4][0], o[4][1], o[4][2], o[4][3],
                            ph[0], ph[1], ph[2], ph[3], c80, c81);
                }
            }
        }

        {   // softmax(kt)
            uint32_t* Pw = smw + OP0 + (kt & 1)*2304;
            const int r0 = wm*16 + g;
#pragma unroll
            for (int nt = 0; nt < 4; nt++) {
                const int cb = 16*wn + 4*nt + tig;
                float p0 = __expf(s[nt][0] - mnew[0]);
                float p1 = __expf(s[nt][1] - mnew[0]);
                float p2 = __expf(s[nt][2] - mnew[1]);
                float p3 = __expf(s[nt][3] - mnew[1]);
                ssum[0] += p0 + p1;
                ssum[1] += p2 + p3;
                __half2 h;
                h = __float22half2_rn(make_float2(p0, p1));
                Pw[(r0    )*SH36 + cb] = *(uint32_t*)&h;
                h = __float22half2_rn(make_float2(p2, p3));
                Pw[(r0 + 8)*SH36 + cb] = *(uint32_t*)&h;
            }
        }
#pragma unroll
        for (int hf = 0; hf < 2; hf++) {
            float sv = ssum[hf];
            sv += __shfl_xor_sync(0xffffffffu, sv, 1);
            sv += __shfl_xor_sync(0xffffffffu, sv, 2);
            if (tig == 0) rsum[(wm*16 + g + 8*hf)*2 + wn] = sv;
        }
        __syncthreads();
        // ======= end region =======

        if (wn == 0 && tig == 0) {
#pragma unroll
            for (int hf = 0; hf < 2; hf++) {
                const int row = wm*16 + g + 8*hf;
                const float ts = rsum[row*2] + rsum[row*2+1];
                l_s[row]  = l_s[row]*alv[hf] + ts;
                m_s[row]  = mnew[hf];
                al_s[row] = alv[hf];
            }
        }
        if (kt < 31) cp_wait<1>(); else cp_wait<0>();
        __syncthreads();
    }

    // ---- epilogue PV(31) ----
    {
        const int rb = r4*16 + g;
        const float a0 = al_s[rb], a1 = al_s[rb + 8];
#pragma unroll
        for (int f = 0; f < 5; f++) {
            o[f][0] *= a0; o[f][1] *= a0;
            o[f][2] *= a1; o[f][3] *= a1;
        }
        const uint32_t pbuf = ap_b0  + (31 & 1)*PBB;
        const uint32_t cbuf = cdh_b0 + (31 & 1)*CDB;
        const uint32_t cbuf8 = cdh8_0 + (31 & 1)*CDB;
#pragma unroll
        for (int ks = 0; ks < 4; ks++) {
            const uint32_t kb = ks * 32;
            uint32_t ph[4];
            ldsm_x4(ph[0], ph[1], ph[2], ph[3], pbuf + kb);
#pragma unroll
            for (int p = 0; p < 2; p++) {
                uint32_t c0A, c1A, c0B, c1B;
                ldsm_x4(c0A, c1A, c0B, c1B, cbuf + p*16*ROW36B + kb);
                const int f0 = 2*p, f1 = 2*p + 1;
                mma_f16(o[f0][0], o[f0][1], o[f0][2], o[f0][3],
                        ph[0], ph[1], ph[2], ph[3], c0A, c1A);
                mma_f16(o[f1][0], o[f1][1], o[f1][2], o[f1][3],
                        ph[0], ph[1], ph[2], ph[3], c0B, c1B);
            }
            {
                uint32_t c80, c81;
                ldsm_x2(c80, c81, cbuf8 + kb);
                mma_f16(o[4][0], o[4][1], o[4][2], o[4][3],
                        ph[0], ph[1], ph[2], ph[3], c80, c81);
            }
        }
    }

    // ---- store out1 ----
    const int rb = r4*16 + g;
    const float inv0 = 1.0f / l_s[rb];
    const float inv1 = 1.0f / l_s[rb + 8];
    const int b = bh >> 3, h = bh & 7;
    const size_t base0 = (size_t)(b*2048 + q0 + rb) * 536 + h*67;
    const size_t base1 = base0 + (size_t)8 * 536;
#pragma unroll
    for (int f = 0; f < 5; f++) {
        if (g2 == 1 && f == 0) continue;
        const int nt = g2*4 + f;
        const int col = nt*8 + 2*tig;
        if (col < WAW) {
            out1[base0 + col] = o[f][0] * inv0;
            out1[base1 + col] = o[f][2] * inv1;
        }
        if (col + 1 < WAW) {
            out1[base0 + col + 1] = o[f][1] * inv0;
            out1[base1 + col + 1] = o[f][3] * inv1;
        }
    }
}

// ======================================================================
extern "C" void kernel_launch(void* const* d_in, const int* in_sizes, int n_in,
                              void* d_out, int out_size)
{
    (void)in_sizes; (void)n_in; (void)out_size;
    const float* x  = (const float*)d_in[0];
    const float* Wq = (const float*)d_in[1];
    const float* Wk = (const float*)d_in[2];
    const float* Wv = (const float*)d_in[3];
    float* out = (float*)d_out;

    cudaFuncSetAttribute(qkv_mma_kernel, cudaFuncAttributeMaxDynamicSharedMemorySize,
                         QKV_SMEM);
    qkv_mma_kernel<<<dim3(8, 64, 3), 256, QKV_SMEM>>>(x, Wq, Wk, Wv,
                                                      out + OUT1_ELEMS);

    cudaFuncSetAttribute(flash_f16_kernel, cudaFuncAttributeMaxDynamicSharedMemorySize,
                         FL_SMEM);
    flash_f16_kernel<<<dim3(32, 32), 256, FL_SMEM>>>(out);
}

// round 16
// speedup vs baseline: 1.3849x; 1.1882x over previous
#include <cuda_runtime.h>
#include <cuda_fp16.h>
#include <math.h>
#include <cstdint>

// Problem constants: B=4, S=2048, Hd=1024, H=8, dk=128, wA=67
#define NBH   32
#define SEQ   2048
#define DKD   128
#define WAW   67
#define OUT1_ELEMS (4*2048*536)

// ---------------- scratch: pre-split fp16 (zero-init pads persist) ----
__device__ __align__(16) __half g_Qhi[NBH*SEQ*DKD];
__device__ __align__(16) __half g_Qlo[NBH*SEQ*DKD];
__device__ __align__(16) __half g_Khi[NBH*SEQ*DKD];     // K: hi only
// cD transposed per 128-key-tile: (bh, kt128, w[72], key[128]); w=67..71 zero
__device__ __align__(16) __half g_cDhi[NBH*16*72*128];

__constant__ float c_lo[8] = { -0.010597401784997278f, 0.032883011666982945f,
                                0.030841381835986965f, -0.18703481171888114f,
                               -0.02798376941698385f,  0.6308807679295904f,
                                0.7148465705525415f,   0.23037781330885523f };
__constant__ float c_hi[8] = { -0.23037781330885523f,  0.7148465705525415f,
                               -0.6308807679295904f,  -0.02798376941698385f,
                                0.18703481171888114f,  0.030841381835986965f,
                               -0.032883011666982945f, -0.010597401784997278f };

__device__ __forceinline__ void mma_f16(float& d0, float& d1, float& d2, float& d3,
                                        uint32_t a0, uint32_t a1, uint32_t a2, uint32_t a3,
                                        uint32_t b0, uint32_t b1) {
    asm("mma.sync.aligned.m16n8k16.row.col.f32.f16.f16.f32 "
        "{%0,%1,%2,%3}, {%4,%5,%6,%7}, {%8,%9}, {%0,%1,%2,%3};"
        : "+f"(d0), "+f"(d1), "+f"(d2), "+f"(d3)
        : "r"(a0), "r"(a1), "r"(a2), "r"(a3), "r"(b0), "r"(b1));
}

__device__ __forceinline__ void ldsm_x4(uint32_t& r0, uint32_t& r1,
                                        uint32_t& r2, uint32_t& r3, uint32_t a) {
    asm volatile("ldmatrix.sync.aligned.m8n8.x4.shared.b16 {%0,%1,%2,%3}, [%4];"
                 : "=r"(r0), "=r"(r1), "=r"(r2), "=r"(r3) : "r"(a));
}
__device__ __forceinline__ void ldsm_x2(uint32_t& r0, uint32_t& r1, uint32_t a) {
    asm volatile("ldmatrix.sync.aligned.m8n8.x2.shared.b16 {%0,%1}, [%2];"
                 : "=r"(r0), "=r"(r1) : "r"(a));
}

__device__ __forceinline__ void split_h2(float x, float y, __half2& hi, __half2& lo) {
    hi = __float22half2_rn(make_float2(x, y));
    float2 b = __half22float2(hi);
    lo = __float22half2_rn(make_float2(x - b.x, y - b.y));
}

__device__ __forceinline__ void cp_async16(uint32_t saddr, const void* g) {
    asm volatile("cp.async.cg.shared.global [%0], [%1], 16;"
                 :: "r"(saddr), "l"(g) : "memory");
}
__device__ __forceinline__ void cp_commit() {
    asm volatile("cp.async.commit_group;" ::: "memory");
}
template<int N>
__device__ __forceinline__ void cp_wait() {
    asm volatile("cp.async.wait_group %0;" :: "n"(N) : "memory");
}

// ======================================================================
// Kernel 1: QKV projection, fp16 m16n8k16 single-term (fp16 mantissa ==
// tf32 mantissa; half the MMA instructions).  Q -> hi/lo split; K -> hi
// only; V-epilogue fuses db4 DWT, writes cD (hi only) transposed.
// ======================================================================
#define TSTR 20                 // b32 row stride (conflict-free for frags)
#define TILE_B32 (128*TSTR)     // 2560 b32 per tile buffer
#define QKV_SMEM (128*132*4)    // 67584 B (Vt staging dominates)

__global__ __launch_bounds__(256, 2) void qkv_mma_kernel(
    const float* __restrict__ x, const float* __restrict__ Wq,
    const float* __restrict__ Wk, const float* __restrict__ Wv,
    float* __restrict__ out2)
{
    extern __shared__ __align__(16) uint32_t smq[];
    // tiles: As[2], Bs[2], each TILE_B32 (total 10240 b32 = 40KB)
    const int tid  = threadIdx.x;
    const int lane = tid & 31;
    const int warp = tid >> 5;
    const int g    = lane >> 2;
    const int tig  = lane & 3;
    const int wm   = warp & 3;
    const int wn   = warp >> 2;

    const int which = blockIdx.z;
    const float* W = (which == 0) ? Wq : ((which == 1) ? Wk : Wv);
    const float scale = (which == 0) ? 0.08838834764831845f : 1.0f;

    const int m0   = blockIdx.y * 128;
    const int head = blockIdx.x;
    const float* xb = x + (size_t)m0 * 1024;
    const float* wb = W + (size_t)head * 128 * 1024;

    const int lr = tid >> 3;          // row 0..31 (+32u)
    const int lf = tid & 7;           // float4 index within 32-k chunk
    const int lc = lf * 2;            // b32 (half2) col

    float c[2][8][4];
#pragma unroll
    for (int mt = 0; mt < 2; mt++)
#pragma unroll
        for (int nt = 0; nt < 8; nt++)
#pragma unroll
            for (int q = 0; q < 4; q++) c[mt][nt][q] = 0.0f;

    // ---- preload chunk 0 ----
    {
#pragma unroll
        for (int u = 0; u < 4; u++) {
            const int r = lr + 32*u;
            const float4 a4 = *(const float4*)(xb + (size_t)r*1024 + lf*4);
            const float4 b4 = *(const float4*)(wb + (size_t)r*1024 + lf*4);
            __half2 h;
            h = __floats2half2_rn(a4.x, a4.y); smq[r*TSTR + lc]     = *(uint32_t*)&h;
            h = __floats2half2_rn(a4.z, a4.w); smq[r*TSTR + lc + 1] = *(uint32_t*)&h;
            h = __floats2half2_rn(b4.x, b4.y); smq[2*TILE_B32 + r*TSTR + lc]     = *(uint32_t*)&h;
            h = __floats2half2_rn(b4.z, b4.w); smq[2*TILE_B32 + r*TSTR + lc + 1] = *(uint32_t*)&h;
        }
    }
    __syncthreads();

    for (int ch = 0; ch < 32; ch++) {
        const int cur = ch & 1;
        float4 pfa[4], pfb[4];
        if (ch < 31) {
            const int kb = (ch + 1) << 5;
#pragma unroll
            for (int u = 0; u < 4; u++) {
                const int r = lr + 32*u;
                pfa[u] = *(const float4*)(xb + (size_t)r*1024 + kb + lf*4);
                pfb[u] = *(const float4*)(wb + (size_t)r*1024 + kb + lf*4);
            }
        }

        const uint32_t* as = smq + cur*TILE_B32;
        const uint32_t* bs = smq + 2*TILE_B32 + cur*TILE_B32;
#pragma unroll
        for (int ks = 0; ks < 2; ks++) {          // 2 k-steps of 16
            const int k0 = ks * 8;
            uint32_t a[2][4];
#pragma unroll
            for (int mt = 0; mt < 2; mt++) {
                const int rb = wm*32 + mt*16 + g;
                a[mt][0] = as[(rb    )*TSTR + k0 + tig];
                a[mt][1] = as[(rb + 8)*TSTR + k0 + tig];
                a[mt][2] = as[(rb    )*TSTR + k0 + tig + 4];
                a[mt][3] = as[(rb + 8)*TSTR + k0 + tig + 4];
            }
#pragma unroll
            for (int nt = 0; nt < 8; nt++) {
                const int nb = wn*64 + nt*8 + g;
                const uint32_t b0 = bs[nb*TSTR + k0 + tig];
                const uint32_t b1 = bs[nb*TSTR + k0 + tig + 4];
#pragma unroll
                for (int mt = 0; mt < 2; mt++)
                    mma_f16(c[mt][nt][0], c[mt][nt][1], c[mt][nt][2], c[mt][nt][3],
                            a[mt][0], a[mt][1], a[mt][2], a[mt][3], b0, b1);
            }
        }

        if (ch < 31) {
            uint32_t* pa0 = smq + (cur^1)*TILE_B32;
            uint32_t* pb0 = smq + 2*TILE_B32 + (cur^1)*TILE_B32;
#pragma unroll
            for (int u = 0; u < 4; u++) {
                const int r = lr + 32*u;
                __half2 h;
                h = __floats2half2_rn(pfa[u].x, pfa[u].y); pa0[r*TSTR + lc]     = *(uint32_t*)&h;
                h = __floats2half2_rn(pfa[u].z, pfa[u].w); pa0[r*TSTR + lc + 1] = *(uint32_t*)&h;
                h = __floats2half2_rn(pfb[u].x, pfb[u].y); pb0[r*TSTR + lc]     = *(uint32_t*)&h;
                h = __floats2half2_rn(pfb[u].z, pfb[u].w); pb0[r*TSTR + lc + 1] = *(uint32_t*)&h;
            }
        }
        __syncthreads();
    }

    if (which == 0) {
        // Q: hi/lo split, pre-scaled
        __half2* Ohi = (__half2*)g_Qhi;
        __half2* Olo = (__half2*)g_Qlo;
#pragma unroll
        for (int mt = 0; mt < 2; mt++) {
            const int m  = m0 + wm*32 + mt*16 + g;
            const int b0_ = m >> 11, sq = m & 2047;
            const size_t row0 = ((size_t)(b0_*8 + head) * 2048 + sq) * 64;
            const size_t row1 = row0 + 8*64;
#pragma unroll
            for (int nt = 0; nt < 8; nt++) {
                const int d2 = wn*32 + nt*4 + tig;
                __half2 h, l;
                split_h2(c[mt][nt][0]*scale, c[mt][nt][1]*scale, h, l);
                Ohi[row0 + d2] = h;  Olo[row0 + d2] = l;
                split_h2(c[mt][nt][2]*scale, c[mt][nt][3]*scale, h, l);
                Ohi[row1 + d2] = h;  Olo[row1 + d2] = l;
            }
        }
    } else if (which == 1) {
        // K: hi only
        __half2* Ohi = (__half2*)g_Khi;
#pragma unroll
        for (int mt = 0; mt < 2; mt++) {
            const int m  = m0 + wm*32 + mt*16 + g;
            const int b0_ = m >> 11, sq = m & 2047;
            const size_t row0 = ((size_t)(b0_*8 + head) * 2048 + sq) * 64;
            const size_t row1 = row0 + 8*64;
#pragma unroll
            for (int nt = 0; nt < 8; nt++) {
                const int d2 = wn*32 + nt*4 + tig;
                Ohi[row0 + d2] = __float22half2_rn(make_float2(c[mt][nt][0], c[mt][nt][1]));
                Ohi[row1 + d2] = __float22half2_rn(make_float2(c[mt][nt][2], c[mt][nt][3]));
            }
        }
    } else {
        float* Vt = (float*)smq;      // [128][132]
        __syncthreads();              // tiles no longer needed
#pragma unroll
        for (int mt = 0; mt < 2; mt++) {
            const int r0 = wm*32 + mt*16 + g;
#pragma unroll
            for (int nt = 0; nt < 8; nt++) {
                const int d = wn*64 + nt*8 + 2*tig;
                *(float2*)(Vt + (r0    )*132 + d) = make_float2(c[mt][nt][0], c[mt][nt][1]);
                *(float2*)(Vt + (r0 + 8)*132 + d) = make_float2(c[mt][nt][2], c[mt][nt][3]);
            }
        }
        __syncthreads();
        const int r    = tid >> 1;
        const int half = tid & 1;
        const int m    = m0 + r;
        const int b0_  = m >> 11, sq = m & 2047;
        const int bh   = b0_*8 + head;
        const int kt_  = sq >> 7, key = sq & 127;
        const size_t rowbase = ((size_t)bh * 2048 + sq) * WAW;
        const size_t cdbase  = ((size_t)bh * 16 + kt_) * 72 * 128 + key;
        const float* v = Vt + r*132;
        for (int t = half; t < WAW; t += 2) {
            float a = 0.0f, d = 0.0f;
#pragma unroll
            for (int k = 0; k < 8; k++) {
                const int j = 2*t + k;
                const int src = (j < 6) ? (5 - j) : ((j < 134) ? (j - 6) : (261 - j));
                const float e = v[src];
                a = fmaf(e, c_lo[7 - k], a);
                d = fmaf(e, c_hi[7 - k], d);
            }
            out2[rowbase + t] = a;
            g_cDhi[cdbase + (size_t)t*128] = __float2half_rn(d);
        }
    }
}

// ======================================================================
// Kernel 2: flash attention, 64q x 64k.  S = (Qhi+Qlo) x Khi (2 MMAs);
// PV = Phi x cDhi (1 MMA), one tile behind, fused with softmax.
// (unchanged from R15 pass)
// ======================================================================
#define SH68 68
#define SH36 36
#define OQHI 0
#define OQLO 4352
#define OKHI 8704
#define OCD0 13056           // 72*36 = 2592 per buffer (x2)
#define OP0  18240           // 64*36 = 2304 per buffer (x2)
#define OCTRL 22848
#define FL_SMEM ((OCTRL + 448) * 4)   // 93,184 B
#define ROW68B (SH68*4)
#define ROW36B (SH36*4)
#define CDB (2592*4)
#define PBB (2304*4)

__global__ __launch_bounds__(256, 2) void flash_f16_kernel(float* __restrict__ out1)
{
    extern __shared__ __align__(16) uint32_t smw[];
    uint32_t* Qhi = smw + OQHI;
    uint32_t* Qlo = smw + OQLO;
    float* rmax = (float*)(smw + OCTRL);
    float* rsum = rmax + 128;
    float* m_s  = rsum + 128;
    float* l_s  = m_s + 64;
    float* al_s = l_s + 64;

    uint32_t sbase;
    asm("{ .reg .u64 t; cvta.to.shared.u64 t, %1; cvt.u32.u64 %0, t; }"
        : "=r"(sbase) : "l"(smw));
    const uint32_t khi_a = sbase + OKHI*4;
    const uint32_t cd_a  = sbase + OCD0*4;

    const int tid  = threadIdx.x;
    const int lane = tid & 31;
    const int warp = tid >> 5;
    const int g    = lane >> 2;
    const int tig  = lane & 3;
    const int wm   = warp & 3;
    const int wn   = warp >> 2;
    const int r4   = warp & 3;
    const int g2   = warp >> 2;

    const int bh = blockIdx.y;
    const int q0 = blockIdx.x * 64;
    const uint4* Qhig = (const uint4*)(g_Qhi + (size_t)bh * SEQ * DKD);
    const uint4* Qlog = (const uint4*)(g_Qlo + (size_t)bh * SEQ * DKD);
    const uint4* Khig = (const uint4*)(g_Khi + (size_t)bh * SEQ * DKD);

    const int cr  = tid >> 4;
    const int cc4 = tid & 15;

    const int rowf  = (lane & 7) + 8*((lane >> 3) & 1);
    const int colf4 = (lane >> 4) * 4;
    const int rowb  = (lane & 7) + 8*(lane >> 4);
    const int colb4 = ((lane >> 3) & 1) * 4;
    const uint32_t aq_hi = sbase + (OQHI + (wm*16 + rowf)*SH68 + colf4)*4;
    const uint32_t aq_lo = sbase + (OQLO + (wm*16 + rowf)*SH68 + colf4)*4;
    const uint32_t bk_hi = sbase + (OKHI + (wn*32 + rowb)*SH68 + colb4)*4;
    const uint32_t ap_b0 = sbase + (OP0 + (r4*16 + rowf)*SH36 + colf4)*4;
    const uint32_t cdh_b0 = sbase + (OCD0 + (g2*32 + rowb)*SH36 + colb4)*4;
    const uint32_t cdh8_0 = sbase + (OCD0 + (g2*32 + 32 + (lane & 7))*SH36 + colb4)*4;

    // ---- prefetch K(0): hi only ----
#pragma unroll
    for (int u = 0; u < 4; u++) {
        const int r = cr + 16*u;
        cp_async16(khi_a + (r*SH68 + cc4*4)*4, Khig + (size_t)r*16 + cc4);
    }
    cp_commit();

    // ---- load Q ----
#pragma unroll
    for (int u = 0; u < 4; u++) {
        const int r = cr + 16*u;
        *(uint4*)&Qhi[r*SH68 + cc4*4] = Qhig[(size_t)(q0 + r)*16 + cc4];
        *(uint4*)&Qlo[r*SH68 + cc4*4] = Qlog[(size_t)(q0 + r)*16 + cc4];
    }
    if (tid < 64) { m_s[tid] = -1e30f; l_s[tid] = 0.0f; }

    float o[5][4];
#pragma unroll
    for (int f = 0; f < 5; f++)
#pragma unroll
        for (int q = 0; q < 4; q++) o[f][q] = 0.0f;

    for (int kt = 0; kt < 32; kt++) {
        cp_wait<0>();
        __syncthreads();
        // ---- cD(kt) prefetch (hi only) into buf[kt&1] ----
        {
            const uint4* ch = (const uint4*)(g_cDhi + ((size_t)bh*16 + (kt >> 1))*72*128);
            const int koff8 = (kt & 1) * 8;
            const uint32_t dst = cd_a + (kt & 1)*CDB;
#pragma unroll
            for (int u = 0; u < 3; u++) {
                const int i = tid + 256*u;
                if (i < 576) {
                    const int w = i >> 3, c = i & 7;
                    cp_async16(dst + (w*SH36 + c*4)*4, ch + (size_t)w*16 + koff8 + c);
                }
            }
            cp_commit();
        }

        // ---- S = (Qhi + Qlo) x Khi : LDSM + 2 MMAs per fragment ----
        float s[4][4];
#pragma unroll
        for (int nt = 0; nt < 4; nt++)
#pragma unroll
            for (int q = 0; q < 4; q++) s[nt][q] = 0.0f;

#pragma unroll 2
        for (int ks = 0; ks < 8; ks++) {
            const uint32_t kb = ks * 32;
            uint32_t ah[4], al_[4];
            ldsm_x4(ah[0], ah[1], ah[2], ah[3], aq_hi + kb);
            ldsm_x4(al_[0], al_[1], al_[2], al_[3], aq_lo + kb);
            uint32_t bh_[2][4];
#pragma unroll
            for (int p = 0; p < 2; p++)
                ldsm_x4(bh_[p][0], bh_[p][1], bh_[p][2], bh_[p][3], bk_hi + p*16*ROW68B + kb);
#pragma unroll
            for (int p = 0; p < 2; p++) {
                mma_f16(s[2*p][0], s[2*p][1], s[2*p][2], s[2*p][3],
                        ah[0], ah[1], ah[2], ah[3], bh_[p][0], bh_[p][1]);
                mma_f16(s[2*p+1][0], s[2*p+1][1], s[2*p+1][2], s[2*p+1][3],
                        ah[0], ah[1], ah[2], ah[3], bh_[p][2], bh_[p][3]);
            }
#pragma unroll
            for (int p = 0; p < 2; p++) {
                mma_f16(s[2*p][0], s[2*p][1], s[2*p][2], s[2*p][3],
                        al_[0], al_[1], al_[2], al_[3], bh_[p][0], bh_[p][1]);
                mma_f16(s[2*p+1][0], s[2*p+1][1], s[2*p+1][2], s[2*p+1][3],
                        al_[0], al_[1], al_[2], al_[3], bh_[p][2], bh_[p][3]);
            }
        }

        // ---- row max ----
        float mx[2];
#pragma unroll
        for (int hf = 0; hf < 2; hf++) {
            float m = -1e30f;
#pragma unroll
            for (int nt = 0; nt < 4; nt++)
                m = fmaxf(m, fmaxf(s[nt][2*hf], s[nt][2*hf+1]));
            m = fmaxf(m, __shfl_xor_sync(0xffffffffu, m, 1));
            m = fmaxf(m, __shfl_xor_sync(0xffffffffu, m, 2));
            mx[hf] = m;
        }
        if (tig == 0) {
#pragma unroll
            for (int hf = 0; hf < 2; hf++)
                rmax[(wm*16 + g + 8*hf)*2 + wn] = mx[hf];
        }
        __syncthreads();

        // ---- prefetch K(kt+1) ----
        if (kt < 31) {
            const int n1 = (kt + 1) * 64;
#pragma unroll
            for (int u = 0; u < 4; u++) {
                const int r = cr + 16*u;
                cp_async16(khi_a + (r*SH68 + cc4*4)*4, Khig + (size_t)(n1 + r)*16 + cc4);
            }
            cp_commit();
        }

        // ======= BARRIER-FREE REGION: PV(kt-1) HMMA ∥ softmax(kt) =======
        float mnew[2], alv[2], ssum[2];
#pragma unroll
        for (int hf = 0; hf < 2; hf++) {
            const int row = wm*16 + g + 8*hf;
            const float tm = fmaxf(rmax[row*2], rmax[row*2+1]);
            const float mo = m_s[row];
            const float mn = fmaxf(mo, tm);
            mnew[hf] = mn;
            alv[hf]  = __expf(mo - mn);
            ssum[hf] = 0.0f;
        }

        if (kt > 0) {
            const int rb = r4*16 + g;
            const float a0 = al_s[rb], a1 = al_s[rb + 8];
#pragma unroll
            for (int f = 0; f < 5; f++) {
                o[f][0] *= a0; o[f][1] *= a0;
                o[f][2] *= a1; o[f][3] *= a1;
            }
            const uint32_t pbuf = ap_b0  + ((kt-1) & 1)*PBB;
            const uint32_t cbuf = cdh_b0 + ((kt-1) & 1)*CDB;
            const uint32_t cbuf8 = cdh8_0 + ((kt-1) & 1)*CDB;
#pragma unroll
            for (int ks = 0; ks < 4; ks++) {
                const uint32_t kb = ks * 32;
                uint32_t ph[4];
                ldsm_x4(ph[0], ph[1], ph[2], ph[3], pbuf + kb);
#pragma unroll
                for (int p = 0; p < 2; p++) {
                    uint32_t c0A, c1A, c0B, c1B;
                    ldsm_x4(c0A, c1A, c0B, c1B, cbuf + p*16*ROW36B + kb);
                    const int f0 = 2*p, f1 = 2*p + 1;
                    mma_f16(o[f0][0], o[f0][1], o[f0][2], o[f0][3],
                            ph[0], ph[1], ph[2], ph[3], c0A, c1A);
                    mma_f16(o[f1][0], o[f1][1], o[f1][2], o[f1][3],
                            ph[0], ph[1], ph[2], ph[3], c0B, c1B);
                }
                {
                    uint32_t c80, c81;
                    ldsm_x2(c80, c81, cbuf8 + kb);
                    mma_f16(o[4][0], o[4][1], o[4][2], o[4][3],
                            ph[0], ph[1], ph[2], ph[3], c80, c81);
                }
            }
        }

        {   // softmax(kt)
            uint32_t* Pw = smw + OP0 + (kt & 1)*2304;
            const int r0 = wm*16 + g;
#pragma unroll
            for (int nt = 0; nt < 4; nt++) {
                const int cb = 16*wn + 4*nt + tig;
                float p0 = __expf(s[nt][0] - mnew[0]);
                float p1 = __expf(s[nt][1] - mnew[0]);
                float p2 = __expf(s[nt][2] - mnew[1]);
                float p3 = __expf(s[nt][3] - mnew[1]);
                ssum[0] += p0 + p1;
                ssum[1] += p2 + p3;
                __half2 h;
                h = __float22half2_rn(make_float2(p0, p1));
                Pw[(r0    )*SH36 + cb] = *(uint32_t*)&h;
                h = __float22half2_rn(make_float2(p2, p3));
                Pw[(r0 + 8)*SH36 + cb] = *(uint32_t*)&h;
            }
        }
#pragma unroll
        for (int hf = 0; hf < 2; hf++) {
            float sv = ssum[hf];
            sv += __shfl_xor_sync(0xffffffffu, sv, 1);
            sv += __shfl_xor_sync(0xffffffffu, sv, 2);
            if (tig == 0) rsum[(wm*16 + g + 8*hf)*2 + wn] = sv;
        }
        __syncthreads();
        // ======= end region =======

        if (wn == 0 && tig == 0) {
#pragma unroll
            for (int hf = 0; hf < 2; hf++) {
                const int row = wm*16 + g + 8*hf;
                const float ts = rsum[row*2] + rsum[row*2+1];
                l_s[row]  = l_s[row]*alv[hf] + ts;
                m_s[row]  = mnew[hf];
                al_s[row] = alv[hf];
            }
        }
        if (kt < 31) cp_wait<1>(); else cp_wait<0>();
        __syncthreads();
    }

    // ---- epilogue PV(31) ----
    {
        const int rb = r4*16 + g;
        const float a0 = al_s[rb], a1 = al_s[rb + 8];
#pragma unroll
        for (int f = 0; f < 5; f++) {
            o[f][0] *= a0; o[f][1] *= a0;
            o[f][2] *= a1; o[f][3] *= a1;
        }
        const uint32_t pbuf = ap_b0  + (31 & 1)*PBB;
        const uint32_t cbuf = cdh_b0 + (31 & 1)*CDB;
        const uint32_t cbuf8 = cdh8_0 + (31 & 1)*CDB;
#pragma unroll
        for (int ks = 0; ks < 4; ks++) {
            const uint32_t kb = ks * 32;
            uint32_t ph[4];
            ldsm_x4(ph[0], ph[1], ph[2], ph[3], pbuf + kb);
#pragma unroll
            for (int p = 0; p < 2; p++) {
                uint32_t c0A, c1A, c0B, c1B;
                ldsm_x4(c0A, c1A, c0B, c1B, cbuf + p*16*ROW36B + kb);
                const int f0 = 2*p, f1 = 2*p + 1;
                mma_f16(o[f0][0], o[f0][1], o[f0][2], o[f0][3],
                        ph[0], ph[1], ph[2], ph[3], c0A, c1A);
                mma_f16(o[f1][0], o[f1][1], o[f1][2], o[f1][3],
                        ph[0], ph[1], ph[2], ph[3], c0B, c1B);
            }
            {
                uint32_t c80, c81;
                ldsm_x2(c80, c81, cbuf8 + kb);
                mma_f16(o[4][0], o[4][1], o[4][2], o[4][3],
                        ph[0], ph[1], ph[2], ph[3], c80, c81);
            }
        }
    }

    // ---- store out1 ----
    const int rb = r4*16 + g;
    const float inv0 = 1.0f / l_s[rb];
    const float inv1 = 1.0f / l_s[rb + 8];
    const int b = bh >> 3, h = bh & 7;
    const size_t base0 = (size_t)(b*2048 + q0 + rb) * 536 + h*67;
    const size_t base1 = base0 + (size_t)8 * 536;
#pragma unroll
    for (int f = 0; f < 5; f++) {
        if (g2 == 1 && f == 0) continue;
        const int nt = g2*4 + f;
        const int col = nt*8 + 2*tig;
        if (col < WAW) {
            out1[base0 + col] = o[f][0] * inv0;
            out1[base1 + col] = o[f][2] * inv1;
        }
        if (col + 1 < WAW) {
            out1[base0 + col + 1] = o[f][1] * inv0;
            out1[base1 + col + 1] = o[f][3] * inv1;
        }
    }
}

// ======================================================================
extern "C" void kernel_launch(void* const* d_in, const int* in_sizes, int n_in,
                              void* d_out, int out_size)
{
    (void)in_sizes; (void)n_in; (void)out_size;
    const float* x  = (const float*)d_in[0];
    const float* Wq = (const float*)d_in[1];
    const float* Wk = (const float*)d_in[2];
    const float* Wv = (const float*)d_in[3];
    float* out = (float*)d_out;

    cudaFuncSetAttribute(qkv_mma_kernel, cudaFuncAttributeMaxDynamicSharedMemorySize,
                         QKV_SMEM);
    qkv_mma_kernel<<<dim3(8, 64, 3), 256, QKV_SMEM>>>(x, Wq, Wk, Wv,
                                                      out + OUT1_ELEMS);

    cudaFuncSetAttribute(flash_f16_kernel, cudaFuncAttributeMaxDynamicSharedMemorySize,
                         FL_SMEM);
    flash_f16_kernel<<<dim3(32, 32), 256, FL_SMEM>>>(out);
}

// round 17
// speedup vs baseline: 1.5298x; 1.1047x over previous
#include <cuda_runtime.h>
#include <cuda_fp16.h>
#include <math.h>
#include <cstdint>

// Problem constants: B=4, S=2048, Hd=1024, H=8, dk=128, wA=67
#define NBH   32
#define SEQ   2048
#define DKD   128
#define WAW   67
#define OUT1_ELEMS (4*2048*536)

// ---------------- scratch: fp16 (zero-init pads persist) ----
__device__ __align__(16) __half g_Qhi[NBH*SEQ*DKD];   // Q: hi only (pre-scaled)
__device__ __align__(16) __half g_Khi[NBH*SEQ*DKD];   // K: hi only
// cD transposed per 128-key-tile: (bh, kt128, w[72], key[128]); w=67..71 zero
__device__ __align__(16) __half g_cDhi[NBH*16*72*128];

__constant__ float c_lo[8] = { -0.010597401784997278f, 0.032883011666982945f,
                                0.030841381835986965f, -0.18703481171888114f,
                               -0.02798376941698385f,  0.6308807679295904f,
                                0.7148465705525415f,   0.23037781330885523f };
__constant__ float c_hi[8] = { -0.23037781330885523f,  0.7148465705525415f,
                               -0.6308807679295904f,  -0.02798376941698385f,
                                0.18703481171888114f,  0.030841381835986965f,
                               -0.032883011666982945f, -0.010597401784997278f };

__device__ __forceinline__ void mma_f16(float& d0, float& d1, float& d2, float& d3,
                                        uint32_t a0, uint32_t a1, uint32_t a2, uint32_t a3,
                                        uint32_t b0, uint32_t b1) {
    asm("mma.sync.aligned.m16n8k16.row.col.f32.f16.f16.f32 "
        "{%0,%1,%2,%3}, {%4,%5,%6,%7}, {%8,%9}, {%0,%1,%2,%3};"
        : "+f"(d0), "+f"(d1), "+f"(d2), "+f"(d3)
        : "r"(a0), "r"(a1), "r"(a2), "r"(a3), "r"(b0), "r"(b1));
}

__device__ __forceinline__ void ldsm_x4(uint32_t& r0, uint32_t& r1,
                                        uint32_t& r2, uint32_t& r3, uint32_t a) {
    asm volatile("ldmatrix.sync.aligned.m8n8.x4.shared.b16 {%0,%1,%2,%3}, [%4];"
                 : "=r"(r0), "=r"(r1), "=r"(r2), "=r"(r3) : "r"(a));
}
__device__ __forceinline__ void ldsm_x2(uint32_t& r0, uint32_t& r1, uint32_t a) {
    asm volatile("ldmatrix.sync.aligned.m8n8.x2.shared.b16 {%0,%1}, [%2];"
                 : "=r"(r0), "=r"(r1) : "r"(a));
}

__device__ __forceinline__ void cp_async16(uint32_t saddr, const void* g) {
    asm volatile("cp.async.cg.shared.global [%0], [%1], 16;"
                 :: "r"(saddr), "l"(g) : "memory");
}
__device__ __forceinline__ void cp_commit() {
    asm volatile("cp.async.commit_group;" ::: "memory");
}
template<int N>
__device__ __forceinline__ void cp_wait() {
    asm volatile("cp.async.wait_group %0;" :: "n"(N) : "memory");
}

// ======================================================================
// Kernel 1: QKV projection, fp16 m16n8k16 single-term.
// Q/K -> fp16 hi; V-epilogue fuses db4 DWT, writes cD transposed fp16.
// ======================================================================
#define TSTR 20                 // b32 row stride (conflict-free for frags)
#define TILE_B32 (128*TSTR)     // 2560 b32 per tile buffer
#define QKV_SMEM (128*132*4)    // 67584 B (Vt staging dominates)

__global__ __launch_bounds__(256, 2) void qkv_mma_kernel(
    const float* __restrict__ x, const float* __restrict__ Wq,
    const float* __restrict__ Wk, const float* __restrict__ Wv,
    float* __restrict__ out2)
{
    extern __shared__ __align__(16) uint32_t smq[];
    const int tid  = threadIdx.x;
    const int lane = tid & 31;
    const int warp = tid >> 5;
    const int g    = lane >> 2;
    const int tig  = lane & 3;
    const int wm   = warp & 3;
    const int wn   = warp >> 2;

    const int which = blockIdx.z;
    const float* W = (which == 0) ? Wq : ((which == 1) ? Wk : Wv);
    const float scale = (which == 0) ? 0.08838834764831845f : 1.0f;

    const int m0   = blockIdx.y * 128;
    const int head = blockIdx.x;
    const float* xb = x + (size_t)m0 * 1024;
    const float* wb = W + (size_t)head * 128 * 1024;

    const int lr = tid >> 3;
    const int lf = tid & 7;
    const int lc = lf * 2;

    float c[2][8][4];
#pragma unroll
    for (int mt = 0; mt < 2; mt++)
#pragma unroll
        for (int nt = 0; nt < 8; nt++)
#pragma unroll
            for (int q = 0; q < 4; q++) c[mt][nt][q] = 0.0f;

    {
#pragma unroll
        for (int u = 0; u < 4; u++) {
            const int r = lr + 32*u;
            const float4 a4 = *(const float4*)(xb + (size_t)r*1024 + lf*4);
            const float4 b4 = *(const float4*)(wb + (size_t)r*1024 + lf*4);
            __half2 h;
            h = __floats2half2_rn(a4.x, a4.y); smq[r*TSTR + lc]     = *(uint32_t*)&h;
            h = __floats2half2_rn(a4.z, a4.w); smq[r*TSTR + lc + 1] = *(uint32_t*)&h;
            h = __floats2half2_rn(b4.x, b4.y); smq[2*TILE_B32 + r*TSTR + lc]     = *(uint32_t*)&h;
            h = __floats2half2_rn(b4.z, b4.w); smq[2*TILE_B32 + r*TSTR + lc + 1] = *(uint32_t*)&h;
        }
    }
    __syncthreads();

    for (int ch = 0; ch < 32; ch++) {
        const int cur = ch & 1;
        float4 pfa[4], pfb[4];
        if (ch < 31) {
            const int kb = (ch + 1) << 5;
#pragma unroll
            for (int u = 0; u < 4; u++) {
                const int r = lr + 32*u;
                pfa[u] = *(const float4*)(xb + (size_t)r*1024 + kb + lf*4);
                pfb[u] = *(const float4*)(wb + (size_t)r*1024 + kb + lf*4);
            }
        }

        const uint32_t* as = smq + cur*TILE_B32;
        const uint32_t* bs = smq + 2*TILE_B32 + cur*TILE_B32;
#pragma unroll
        for (int ks = 0; ks < 2; ks++) {
            const int k0 = ks * 8;
            uint32_t a[2][4];
#pragma unroll
            for (int mt = 0; mt < 2; mt++) {
                const int rb = wm*32 + mt*16 + g;
                a[mt][0] = as[(rb    )*TSTR + k0 + tig];
                a[mt][1] = as[(rb + 8)*TSTR + k0 + tig];
                a[mt][2] = as[(rb    )*TSTR + k0 + tig + 4];
                a[mt][3] = as[(rb + 8)*TSTR + k0 + tig + 4];
            }
#pragma unroll
            for (int nt = 0; nt < 8; nt++) {
                const int nb = wn*64 + nt*8 + g;
                const uint32_t b0 = bs[nb*TSTR + k0 + tig];
                const uint32_t b1 = bs[nb*TSTR + k0 + tig + 4];
#pragma unroll
                for (int mt = 0; mt < 2; mt++)
                    mma_f16(c[mt][nt][0], c[mt][nt][1], c[mt][nt][2], c[mt][nt][3],
                            a[mt][0], a[mt][1], a[mt][2], a[mt][3], b0, b1);
            }
        }

        if (ch < 31) {
            uint32_t* pa0 = smq + (cur^1)*TILE_B32;
            uint32_t* pb0 = smq + 2*TILE_B32 + (cur^1)*TILE_B32;
#pragma unroll
            for (int u = 0; u < 4; u++) {
                const int r = lr + 32*u;
                __half2 h;
                h = __floats2half2_rn(pfa[u].x, pfa[u].y); pa0[r*TSTR + lc]     = *(uint32_t*)&h;
                h = __floats2half2_rn(pfa[u].z, pfa[u].w); pa0[r*TSTR + lc + 1] = *(uint32_t*)&h;
                h = __floats2half2_rn(pfb[u].x, pfb[u].y); pb0[r*TSTR + lc]     = *(uint32_t*)&h;
                h = __floats2half2_rn(pfb[u].z, pfb[u].w); pb0[r*TSTR + lc + 1] = *(uint32_t*)&h;
            }
        }
        __syncthreads();
    }

    if (which < 2) {
        // Q (scaled) and K: fp16 hi-only store
        __half2* Ohi = (which == 0) ? (__half2*)g_Qhi : (__half2*)g_Khi;
#pragma unroll
        for (int mt = 0; mt < 2; mt++) {
            const int m  = m0 + wm*32 + mt*16 + g;
            const int b0_ = m >> 11, sq = m & 2047;
            const size_t row0 = ((size_t)(b0_*8 + head) * 2048 + sq) * 64;
            const size_t row1 = row0 + 8*64;
#pragma unroll
            for (int nt = 0; nt < 8; nt++) {
                const int d2 = wn*32 + nt*4 + tig;
                Ohi[row0 + d2] = __floats2half2_rn(c[mt][nt][0]*scale, c[mt][nt][1]*scale);
                Ohi[row1 + d2] = __floats2half2_rn(c[mt][nt][2]*scale, c[mt][nt][3]*scale);
            }
        }
    } else {
        float* Vt = (float*)smq;      // [128][132]
        __syncthreads();
#pragma unroll
        for (int mt = 0; mt < 2; mt++) {
            const int r0 = wm*32 + mt*16 + g;
#pragma unroll
            for (int nt = 0; nt < 8; nt++) {
                const int d = wn*64 + nt*8 + 2*tig;
                *(float2*)(Vt + (r0    )*132 + d) = make_float2(c[mt][nt][0], c[mt][nt][1]);
                *(float2*)(Vt + (r0 + 8)*132 + d) = make_float2(c[mt][nt][2], c[mt][nt][3]);
            }
        }
        __syncthreads();
        const int r    = tid >> 1;
        const int half = tid & 1;
        const int m    = m0 + r;
        const int b0_  = m >> 11, sq = m & 2047;
        const int bh   = b0_*8 + head;
        const int kt_  = sq >> 7, key = sq & 127;
        const size_t rowbase = ((size_t)bh * 2048 + sq) * WAW;
        const size_t cdbase  = ((size_t)bh * 16 + kt_) * 72 * 128 + key;
        const float* v = Vt + r*132;
        for (int t = half; t < WAW; t += 2) {
            float a = 0.0f, d = 0.0f;
#pragma unroll
            for (int k = 0; k < 8; k++) {
                const int j = 2*t + k;
                const int src = (j < 6) ? (5 - j) : ((j < 134) ? (j - 6) : (261 - j));
                const float e = v[src];
                a = fmaf(e, c_lo[7 - k], a);
                d = fmaf(e, c_hi[7 - k], d);
            }
            out2[rowbase + t] = a;
            g_cDhi[cdbase + (size_t)t*128] = __float2half_rn(d);
        }
    }
}

// ======================================================================
// Kernel 2: flash attention, 64q x 64k, pure fp16: S = Qhi x Khi (1 MMA);
// PV = Phi x cDhi (1 MMA), one tile behind, fused with softmax.
// SMEM 75.8 KB -> 2 CTAs/SM with headroom.
// ======================================================================
#define SH68 68
#define SH36 36
#define OQHI 0
#define OKHI 4352
#define OCD0 8704            // 72*36 = 2592 per buffer (x2)
#define OP0  13888           // 64*36 = 2304 per buffer (x2)
#define OCTRL 18496
#define FL_SMEM ((OCTRL + 448) * 4)   // 75,776 B
#define ROW68B (SH68*4)
#define ROW36B (SH36*4)
#define CDB (2592*4)
#define PBB (2304*4)

__global__ __launch_bounds__(256, 2) void flash_f16_kernel(float* __restrict__ out1)
{
    extern __shared__ __align__(16) uint32_t smw[];
    uint32_t* Qhi = smw + OQHI;
    float* rmax = (float*)(smw + OCTRL);
    float* rsum = rmax + 128;
    float* m_s  = rsum + 128;
    float* l_s  = m_s + 64;
    float* al_s = l_s + 64;

    uint32_t sbase;
    asm("{ .reg .u64 t; cvta.to.shared.u64 t, %1; cvt.u32.u64 %0, t; }"
        : "=r"(sbase) : "l"(smw));
    const uint32_t khi_a = sbase + OKHI*4;
    const uint32_t cd_a  = sbase + OCD0*4;

    const int tid  = threadIdx.x;
    const int lane = tid & 31;
    const int warp = tid >> 5;
    const int g    = lane >> 2;
    const int tig  = lane & 3;
    const int wm   = warp & 3;
    const int wn   = warp >> 2;
    const int r4   = warp & 3;
    const int g2   = warp >> 2;

    const int bh = blockIdx.y;
    const int q0 = blockIdx.x * 64;
    const uint4* Qhig = (const uint4*)(g_Qhi + (size_t)bh * SEQ * DKD);
    const uint4* Khig = (const uint4*)(g_Khi + (size_t)bh * SEQ * DKD);

    const int cr  = tid >> 4;
    const int cc4 = tid & 15;

    const int rowf  = (lane & 7) + 8*((lane >> 3) & 1);
    const int colf4 = (lane >> 4) * 4;
    const int rowb  = (lane & 7) + 8*(lane >> 4);
    const int colb4 = ((lane >> 3) & 1) * 4;
    const uint32_t aq_hi = sbase + (OQHI + (wm*16 + rowf)*SH68 + colf4)*4;
    const uint32_t bk_hi = sbase + (OKHI + (wn*32 + rowb)*SH68 + colb4)*4;
    const uint32_t ap_b0 = sbase + (OP0 + (r4*16 + rowf)*SH36 + colf4)*4;
    const uint32_t cdh_b0 = sbase + (OCD0 + (g2*32 + rowb)*SH36 + colb4)*4;
    const uint32_t cdh8_0 = sbase + (OCD0 + (g2*32 + 32 + (lane & 7))*SH36 + colb4)*4;

    // ---- prefetch K(0): hi only ----
#pragma unroll
    for (int u = 0; u < 4; u++) {
        const int r = cr + 16*u;
        cp_async16(khi_a + (r*SH68 + cc4*4)*4, Khig + (size_t)r*16 + cc4);
    }
    cp_commit();

    // ---- load Q (hi only) ----
#pragma unroll
    for (int u = 0; u < 4; u++) {
        const int r = cr + 16*u;
        *(uint4*)&Qhi[r*SH68 + cc4*4] = Qhig[(size_t)(q0 + r)*16 + cc4];
    }
    if (tid < 64) { m_s[tid] = -1e30f; l_s[tid] = 0.0f; }

    float o[5][4];
#pragma unroll
    for (int f = 0; f < 5; f++)
#pragma unroll
        for (int q = 0; q < 4; q++) o[f][q] = 0.0f;

    for (int kt = 0; kt < 32; kt++) {
        cp_wait<0>();
        __syncthreads();
        // ---- cD(kt) prefetch into buf[kt&1] ----
        {
            const uint4* ch = (const uint4*)(g_cDhi + ((size_t)bh*16 + (kt >> 1))*72*128);
            const int koff8 = (kt & 1) * 8;
            const uint32_t dst = cd_a + (kt & 1)*CDB;
#pragma unroll
            for (int u = 0; u < 3; u++) {
                const int i = tid + 256*u;
                if (i < 576) {
                    const int w = i >> 3, c = i & 7;
                    cp_async16(dst + (w*SH36 + c*4)*4, ch + (size_t)w*16 + koff8 + c);
                }
            }
            cp_commit();
        }

        // ---- S = Qhi x Khi : LDSM + 1 MMA per fragment ----
        float s[4][4];
#pragma unroll
        for (int nt = 0; nt < 4; nt++)
#pragma unroll
            for (int q = 0; q < 4; q++) s[nt][q] = 0.0f;

#pragma unroll 2
        for (int ks = 0; ks < 8; ks++) {
            const uint32_t kb = ks * 32;
            uint32_t ah[4];
            ldsm_x4(ah[0], ah[1], ah[2], ah[3], aq_hi + kb);
            uint32_t bh_[2][4];
#pragma unroll
            for (int p = 0; p < 2; p++)
                ldsm_x4(bh_[p][0], bh_[p][1], bh_[p][2], bh_[p][3], bk_hi + p*16*ROW68B + kb);
#pragma unroll
            for (int p = 0; p < 2; p++) {
                mma_f16(s[2*p][0], s[2*p][1], s[2*p][2], s[2*p][3],
                        ah[0], ah[1], ah[2], ah[3], bh_[p][0], bh_[p][1]);
                mma_f16(s[2*p+1][0], s[2*p+1][1], s[2*p+1][2], s[2*p+1][3],
                        ah[0], ah[1], ah[2], ah[3], bh_[p][2], bh_[p][3]);
            }
        }

        // ---- row max ----
        float mx[2];
#pragma unroll
        for (int hf = 0; hf < 2; hf++) {
            float m = -1e30f;
#pragma unroll
            for (int nt = 0; nt < 4; nt++)
                m = fmaxf(m, fmaxf(s[nt][2*hf], s[nt][2*hf+1]));
            m = fmaxf(m, __shfl_xor_sync(0xffffffffu, m, 1));
            m = fmaxf(m, __shfl_xor_sync(0xffffffffu, m, 2));
            mx[hf] = m;
        }
        if (tig == 0) {
#pragma unroll
            for (int hf = 0; hf < 2; hf++)
                rmax[(wm*16 + g + 8*hf)*2 + wn] = mx[hf];
        }
        __syncthreads();

        // ---- prefetch K(kt+1) ----
        if (kt < 31) {
            const int n1 = (kt + 1) * 64;
#pragma unroll
            for (int u = 0; u < 4; u++) {
                const int r = cr + 16*u;
                cp_async16(khi_a + (r*SH68 + cc4*4)*4, Khig + (size_t)(n1 + r)*16 + cc4);
            }
            cp_commit();
        }

        // ======= BARRIER-FREE REGION: PV(kt-1) HMMA ∥ softmax(kt) =======
        float mnew[2], alv[2], ssum[2];
#pragma unroll
        for (int hf = 0; hf < 2; hf++) {
            const int row = wm*16 + g + 8*hf;
            const float tm = fmaxf(rmax[row*2], rmax[row*2+1]);
            const float mo = m_s[row];
            const float mn = fmaxf(mo, tm);
            mnew[hf] = mn;
            alv[hf]  = __expf(mo - mn);
            ssum[hf] = 0.0f;
        }

        if (kt > 0) {
            const int rb = r4*16 + g;
            const float a0 = al_s[rb], a1 = al_s[rb + 8];
#pragma unroll
            for (int f = 0; f < 5; f++) {
                o[f][0] *= a0; o[f][1] *= a0;
                o[f][2] *= a1; o[f][3] *= a1;
            }
            const uint32_t pbuf = ap_b0  + ((kt-1) & 1)*PBB;
            const uint32_t cbuf = cdh_b0 + ((kt-1) & 1)*CDB;
            const uint32_t cbuf8 = cdh8_0 + ((kt-1) & 1)*CDB;
#pragma unroll
            for (int ks = 0; ks < 4; ks++) {
                const uint32_t kb = ks * 32;
                uint32_t ph[4];
                ldsm_x4(ph[0], ph[1], ph[2], ph[3], pbuf + kb);
#pragma unroll
                for (int p = 0; p < 2; p++) {
                    uint32_t c0A, c1A, c0B, c1B;
                    ldsm_x4(c0A, c1A, c0B, c1B, cbuf + p*16*ROW36B + kb);
                    const int f0 = 2*p, f1 = 2*p + 1;
                    mma_f16(o[f0][0], o[f0][1], o[f0][2], o[f0][3],
                            ph[0], ph[1], ph[2], ph[3], c0A, c1A);
                    mma_f16(o[f1][0], o[f1][1], o[f1][2], o[f1][3],
                            ph[0], ph[1], ph[2], ph[3], c0B, c1B);
                }
                {
                    uint32_t c80, c81;
                    ldsm_x2(c80, c81, cbuf8 + kb);
                    mma_f16(o[4][0], o[4][1], o[4][2], o[4][3],
                            ph[0], ph[1], ph[2], ph[3], c80, c81);
                }
            }
        }

        {   // softmax(kt)
            uint32_t* Pw = smw + OP0 + (kt & 1)*2304;
            const int r0 = wm*16 + g;
#pragma unroll
            for (int nt = 0; nt < 4; nt++) {
                const int cb = 16*wn + 4*nt + tig;
                float p0 = __expf(s[nt][0] - mnew[0]);
                float p1 = __expf(s[nt][1] - mnew[0]);
                float p2 = __expf(s[nt][2] - mnew[1]);
                float p3 = __expf(s[nt][3] - mnew[1]);
                ssum[0] += p0 + p1;
                ssum[1] += p2 + p3;
                __half2 h;
                h = __float22half2_rn(make_float2(p0, p1));
                Pw[(r0    )*SH36 + cb] = *(uint32_t*)&h;
                h = __float22half2_rn(make_float2(p2, p3));
                Pw[(r0 + 8)*SH36 + cb] = *(uint32_t*)&h;
            }
        }
#pragma unroll
        for (int hf = 0; hf < 2; hf++) {
            float sv = ssum[hf];
            sv += __shfl_xor_sync(0xffffffffu, sv, 1);
            sv += __shfl_xor_sync(0xffffffffu, sv, 2);
            if (tig == 0) rsum[(wm*16 + g + 8*hf)*2 + wn] = sv;
        }
        __syncthreads();
        // ======= end region =======

        if (wn == 0 && tig == 0) {
#pragma unroll
            for (int hf = 0; hf < 2; hf++) {
                const int row = wm*16 + g + 8*hf;
                const float ts = rsum[row*2] + rsum[row*2+1];
                l_s[row]  = l_s[row]*alv[hf] + ts;
                m_s[row]  = mnew[hf];
                al_s[row] = alv[hf];
            }
        }
        if (kt < 31) cp_wait<1>(); else cp_wait<0>();
        __syncthreads();
    }

    // ---- epilogue PV(31) ----
    {
        const int rb = r4*16 + g;
        const float a0 = al_s[rb], a1 = al_s[rb + 8];
#pragma unroll
        for (int f = 0; f < 5; f++) {
            o[f][0] *= a0; o[f][1] *= a0;
            o[f][2] *= a1; o[f][3] *= a1;
        }
        const uint32_t pbuf = ap_b0  + (31 & 1)*PBB;
        const uint32_t cbuf = cdh_b0 + (31 & 1)*CDB;
        const uint32_t cbuf8 = cdh8_0 + (31 & 1)*CDB;
#pragma unroll
        for (int ks = 0; ks < 4; ks++) {
            const uint32_t kb = ks * 32;
            uint32_t ph[4];
            ldsm_x4(ph[0], ph[1], ph[2], ph[3], pbuf + kb);
#pragma unroll
            for (int p = 0; p < 2; p++) {
                uint32_t c0A, c1A, c0B, c1B;
                ldsm_x4(c0A, c1A, c0B, c1B, cbuf + p*16*ROW36B + kb);
                const int f0 = 2*p, f1 = 2*p + 1;
                mma_f16(o[f0][0], o[f0][1], o[f0][2], o[f0][3],
                        ph[0], ph[1], ph[2], ph[3], c0A, c1A);
                mma_f16(o[f1][0], o[f1][1], o[f1][2], o[f1][3],
                        ph[0], ph[1], ph[2], ph[3], c0B, c1B);
            }
            {
                uint32_t c80, c81;
                ldsm_x2(c80, c81, cbuf8 + kb);
                mma_f16(o[4][0], o[4][1], o[4][2], o[4][3],
                        ph[0], ph[1], ph[2], ph[3], c80, c81);
            }
        }
    }

    // ---- store out1 ----
    const int rb = r4*16 + g;
    const float inv0 = 1.0f / l_s[rb];
    const float inv1 = 1.0f / l_s[rb + 8];
    const int b = bh >> 3, h = bh & 7;
    const size_t base0 = (size_t)(b*2048 + q0 + rb) * 536 + h*67;
    const size_t base1 = base0 + (size_t)8 * 536;
#pragma unroll
    for (int f = 0; f < 5; f++) {
        if (g2 == 1 && f == 0) continue;
        const int nt = g2*4 + f;
        const int col = nt*8 + 2*tig;
        if (col < WAW) {
            out1[base0 + col] = o[f][0] * inv0;
            out1[base1 + col] = o[f][2] * inv1;
        }
        if (col + 1 < WAW) {
            out1[base0 + col + 1] = o[f][1] * inv0;
            out1[base1 + col + 1] = o[f][3] * inv1;
        }
    }
}

// ======================================================================
extern "C" void kernel_launch(void* const* d_in, const int* in_sizes, int n_in,
                              void* d_out, int out_size)
{
    (void)in_sizes; (void)n_in; (void)out_size;
    const float* x  = (const float*)d_in[0];
    const float* Wq = (const float*)d_in[1];
    const float* Wk = (const float*)d_in[2];
    const float* Wv = (const float*)d_in[3];
    float* out = (float*)d_out;

    cudaFuncSetAttribute(qkv_mma_kernel, cudaFuncAttributeMaxDynamicSharedMemorySize,
                         QKV_SMEM);
    qkv_mma_kernel<<<dim3(8, 64, 3), 256, QKV_SMEM>>>(x, Wq, Wk, Wv,
                                                      out + OUT1_ELEMS);

    cudaFuncSetAttribute(flash_f16_kernel, cudaFuncAttributeMaxDynamicSharedMemorySize,
                         FL_SMEM);
    flash_f16_kernel<<<dim3(32, 32), 256, FL_SMEM>>>(out);
}